// round 13
// baseline (speedup 1.0000x reference)
#include <cuda_runtime.h>
#include <cuda_fp16.h>
#include <math.h>
#include <stdint.h>

#define S_LEN   2048
#define BATCH   2
#define HID     2048
#define NHEADS  32
#define KVHEADS 8
#define HDIM    64
#define MROWS   (BATCH * S_LEN)     // 4096
#define KVDIM   (KVHEADS * HDIM)    // 512
#define QKVN    (HID + 2 * KVDIM)   // 3072

// ---------------- scratch (static device globals; no allocations) ----------
__device__ __half g_xh [(size_t)MROWS * HID];
__device__ __half g_xl [(size_t)MROWS * HID];
__device__ __half g_w3 [(size_t)QKVN * HID];
__device__ __half g_wo [(size_t)HID * HID];
__device__ __half g_ah [(size_t)MROWS * HID];
__device__ __half g_al [(size_t)MROWS * HID];

__device__ __half g_qh [(size_t)MROWS * HID];
__device__ __half g_ql [(size_t)MROWS * HID];
__device__ __half g_k16[(size_t)MROWS * KVDIM];
__device__ __half g_v16[(size_t)MROWS * KVDIM];

__device__ float g_rc[S_LEN * 32];
__device__ float g_rs[S_LEN * 32];

// ============================================================================
// PTX helpers (plain sm_103-safe)
// ============================================================================
__device__ __forceinline__ uint32_t smem_to_u32(const void* p) {
    uint32_t a;
    asm("{ .reg .u64 t; cvta.to.shared.u64 t, %1; cvt.u32.u64 %0, t; }"
        : "=r"(a) : "l"(p));
    return a;
}

#define CP_ASYNC16(smem, gmem) \
    asm volatile("cp.async.cg.shared.global [%0], [%1], 16;" \
                 :: "r"(smem), "l"(gmem) : "memory")
#define CP_COMMIT() asm volatile("cp.async.commit_group;" ::: "memory")
#define CP_WAIT(n)  asm volatile("cp.async.wait_group %0;" :: "n"(n) : "memory")

__device__ __forceinline__ void ldsm_x4(uint32_t* r, uint32_t addr) {
    asm volatile("ldmatrix.sync.aligned.m8n8.x4.shared.b16 {%0,%1,%2,%3}, [%4];"
        : "=r"(r[0]), "=r"(r[1]), "=r"(r[2]), "=r"(r[3]) : "r"(addr));
}
__device__ __forceinline__ void ldsm_x2(uint32_t* r, uint32_t addr) {
    asm volatile("ldmatrix.sync.aligned.m8n8.x2.shared.b16 {%0,%1}, [%2];"
        : "=r"(r[0]), "=r"(r[1]) : "r"(addr));
}
__device__ __forceinline__ void ldsm_x2_trans(uint32_t* r, uint32_t addr) {
    asm volatile("ldmatrix.sync.aligned.m8n8.x2.trans.shared.b16 {%0,%1}, [%2];"
        : "=r"(r[0]), "=r"(r[1]) : "r"(addr));
}

__device__ __forceinline__ void mma16816(float* d, const uint32_t* a, const uint32_t* b) {
    asm volatile(
        "mma.sync.aligned.m16n8k16.row.col.f32.f16.f16.f32 "
        "{%0,%1,%2,%3}, {%4,%5,%6,%7}, {%8,%9}, {%0,%1,%2,%3};"
        : "+f"(d[0]), "+f"(d[1]), "+f"(d[2]), "+f"(d[3])
        : "r"(a[0]), "r"(a[1]), "r"(a[2]), "r"(a[3]), "r"(b[0]), "r"(b[1]));
}

__device__ __forceinline__ void pack_hilo(float a, float b, uint32_t& hi, uint32_t& lo) {
    __half ha = __float2half_rn(a);
    __half hb = __float2half_rn(b);
    __half2 H; H.x = ha; H.y = hb;
    hi = *reinterpret_cast<uint32_t*>(&H);
    __half2 L;
    L.x = __float2half_rn(a - __half2float(ha));
    L.y = __float2half_rn(b - __half2float(hb));
    lo = *reinterpret_cast<uint32_t*>(&L);
}

// ============================================================================
// vectorized fp32 -> fp16 split / convert
// ============================================================================
__global__ void split_fp16_v4(const float4* __restrict__ in,
                              uint2* __restrict__ hi, uint2* __restrict__ lo, int n4)
{
    int i = blockIdx.x * blockDim.x + threadIdx.x;
    if (i >= n4) return;
    float4 v = in[i];
    __half2 h0 = __floats2half2_rn(v.x, v.y);
    __half2 h1 = __floats2half2_rn(v.z, v.w);
    __half2 l0 = __floats2half2_rn(v.x - __low2float(h0),  v.y - __high2float(h0));
    __half2 l1 = __floats2half2_rn(v.z - __low2float(h1),  v.w - __high2float(h1));
    uint2 H = {*reinterpret_cast<uint32_t*>(&h0), *reinterpret_cast<uint32_t*>(&h1)};
    uint2 L = {*reinterpret_cast<uint32_t*>(&l0), *reinterpret_cast<uint32_t*>(&l1)};
    hi[i] = H;
    lo[i] = L;
}

// fused Wq|Wk|Wv -> w3  and  Wo -> wo  (one launch)
__global__ void conv_weights_v4(const float4* __restrict__ wq, const float4* __restrict__ wk,
                                const float4* __restrict__ wv, const float4* __restrict__ woin,
                                uint2* __restrict__ w3, uint2* __restrict__ wo)
{
    const int nq = HID * HID / 4;
    const int nk = KVDIM * HID / 4;
    const int n3 = nq + 2 * nk;
    const int tot = n3 + nq;
    int i = blockIdx.x * blockDim.x + threadIdx.x;
    if (i >= tot) return;
    float4 v;
    uint2* dst;
    int oi;
    if (i < nq)            { v = wq[i];            dst = w3; oi = i; }
    else if (i < nq + nk)  { v = wk[i - nq];       dst = w3; oi = i; }
    else if (i < n3)       { v = wv[i - nq - nk];  dst = w3; oi = i; }
    else                   { v = woin[i - n3];     dst = wo; oi = i - n3; }
    __half2 h0 = __floats2half2_rn(v.x, v.y);
    __half2 h1 = __floats2half2_rn(v.z, v.w);
    uint2 H = {*reinterpret_cast<uint32_t*>(&h0), *reinterpret_cast<uint32_t*>(&h1)};
    dst[oi] = H;
}

// ============================================================================
// RoPE table
// ============================================================================
__global__ void rope_table(float* __restrict__ ct, float* __restrict__ st)
{
    int t = blockIdx.x * blockDim.x + threadIdx.x;
    if (t >= S_LEN * 32) return;
    int pos  = t >> 5;
    int pair = t & 31;
    float inv = (float)exp(-(double)pair * (9.210340371976184 / 32.0));
    float a = (float)pos * inv;
    float s, c;
    sincosf(a, &s, &c);
    ct[t] = c;
    st[t] = s;
}

// ============================================================================
// fp16 2-term GEMM via mma.sync, 2-stage cp.async.
// CTA 128x128, 4 warps (128 threads), warp tile 64x64 (warp grid 2x2):
//   A smem redundancy 2, B redundancy 2 -> 96 bytes/HMMA (was 128).
// ============================================================================
#define BM 128
#define BN 128
#define BK 32
#define ROWB   80
#define ASZ    (128 * ROWB)
#define STAGE  (3 * ASZ)                 // Ah, Al, B tiles
#define GEMM_SMEM (2 * STAGE)            // 61440 B -> 2 CTAs/SM

__global__ __launch_bounds__(128) void gemm_mma(
    const __half* __restrict__ Ah, const __half* __restrict__ Al,
    const __half* __restrict__ B,
    float* __restrict__ C, int M, int N, int K,
    int qkv_mode,
    const float* __restrict__ rc, const float* __restrict__ rs,
    __half* __restrict__ qh, __half* __restrict__ ql,
    __half* __restrict__ k16, __half* __restrict__ v16)
{
    extern __shared__ char smem[];
    const uint32_t sbase = smem_to_u32(smem);

    const int tid  = threadIdx.x;
    const int wid  = tid >> 5;
    const int lane = tid & 31;
    const int wm   = wid >> 1;        // 0..1 (64-row band)
    const int wn   = wid & 1;         // 0..1 (64-col band = one head)
    const int bm   = blockIdx.y * BM;
    const int bn   = blockIdx.x * BN;

    const __half* gAh = Ah + (size_t)bm * K;
    const __half* gAl = Al + (size_t)bm * K;
    const __half* gB  = B  + (size_t)bn * K;

    const int NC = K / BK;

    // loader: 128 threads, one row each, 4x16B segments per tile
    const int lr = tid;
    auto issue = [&](int kc, int buf) {
        const uint32_t sb = sbase + buf * STAGE;
        const uint32_t so = (uint32_t)(lr * ROWB);
        const size_t g = (size_t)lr * K + (size_t)kc * BK;
#pragma unroll
        for (int s = 0; s < 4; ++s) {
            CP_ASYNC16(sb + so + s * 16,           gAh + g + s * 8);
            CP_ASYNC16(sb + ASZ + so + s * 16,     gAl + g + s * 8);
            CP_ASYNC16(sb + 2 * ASZ + so + s * 16, gB  + g + s * 8);
        }
        CP_COMMIT();
    };

    float acc[4][8][4];
#pragma unroll
    for (int i = 0; i < 4; ++i)
#pragma unroll
        for (int j = 0; j < 8; ++j)
#pragma unroll
            for (int c = 0; c < 4; ++c) acc[i][j][c] = 0.f;

    const uint32_t a_row  = (uint32_t)(wm * 64 + (lane & 15));
    const uint32_t a_colb = (uint32_t)((lane >> 4) * 16);
    const uint32_t bp_row = (uint32_t)(wn * 64 + ((lane >> 4) << 3) + (lane & 7));
    const uint32_t bp_sel = (uint32_t)(((lane >> 3) & 1) * 16);

    issue(0, 0);
    issue(1, 1);

    for (int kt = 0; kt < NC; ++kt) {
        const int buf = kt & 1;
        if (kt + 2 <= NC) { CP_WAIT(1); }
        else              { CP_WAIT(0); }
        __syncthreads();

        const uint32_t sAh = sbase + buf * STAGE;
        const uint32_t sAl = sAh + ASZ;
        const uint32_t sB  = sAh + 2 * ASZ;

#pragma unroll
        for (int ks = 0; ks < 2; ++ks) {
            const uint32_t kofs = ks * 32;

            uint32_t ah[4][4], al[4][4], bb[4][4];
#pragma unroll
            for (int mt = 0; mt < 4; ++mt) {
                uint32_t off = (a_row + mt * 16) * ROWB + a_colb + kofs;
                ldsm_x4(ah[mt], sAh + off);
                ldsm_x4(al[mt], sAl + off);
            }
#pragma unroll
            for (int ntp = 0; ntp < 4; ++ntp) {
                uint32_t off = (bp_row + ntp * 16) * ROWB + bp_sel + kofs;
                ldsm_x4(bb[ntp], sB + off);
            }
#pragma unroll
            for (int mt = 0; mt < 4; ++mt)
#pragma unroll
                for (int nt = 0; nt < 8; ++nt) {
                    const uint32_t* bf = &bb[nt >> 1][(nt & 1) * 2];
                    mma16816(acc[mt][nt], ah[mt], bf);
                    mma16816(acc[mt][nt], al[mt], bf);
                }
        }
        __syncthreads();

        if (kt + 2 < NC) issue(kt + 2, buf);
    }

    const int er = lane >> 2;
    const int ec = (lane & 3) * 2;

    if (!qkv_mode) {
#pragma unroll
        for (int mt = 0; mt < 4; ++mt) {
            const int row0 = bm + wm * 64 + mt * 16 + er;
#pragma unroll
            for (int nt = 0; nt < 8; ++nt) {
                const int col = bn + wn * 64 + nt * 8 + ec;
                float2 v0 = {acc[mt][nt][0], acc[mt][nt][1]};
                float2 v1 = {acc[mt][nt][2], acc[mt][nt][3]};
                *(float2*)(C + (size_t)row0 * N + col)       = v0;
                *(float2*)(C + (size_t)(row0 + 8) * N + col) = v1;
            }
        }
        return;
    }

    // ---- fused QKV epilogue: rope + fp16 conversion (64-col band = 1 head) ----
    const int gc0 = bn + wn * 64;

    if (gc0 < HID) {
#pragma unroll
        for (int mt = 0; mt < 4; ++mt) {
            const int r0 = bm + wm * 64 + mt * 16 + er;
            const int r1 = r0 + 8;
            const int p0 = r0 & (S_LEN - 1), p1 = r1 & (S_LEN - 1);
#pragma unroll
            for (int nt = 0; nt < 4; ++nt) {
                const int d = nt * 8 + ec;
                float cv00 = rc[p0 * 32 + d],     sv00 = rs[p0 * 32 + d];
                float cv01 = rc[p0 * 32 + d + 1], sv01 = rs[p0 * 32 + d + 1];
                float cv10 = rc[p1 * 32 + d],     sv10 = rs[p1 * 32 + d];
                float cv11 = rc[p1 * 32 + d + 1], sv11 = rs[p1 * 32 + d + 1];
                float x00 = acc[mt][nt][0],     x01 = acc[mt][nt][1];
                float x10 = acc[mt][nt][2],     x11 = acc[mt][nt][3];
                float z00 = acc[mt][nt + 4][0], z01 = acc[mt][nt + 4][1];
                float z10 = acc[mt][nt + 4][2], z11 = acc[mt][nt + 4][3];
                uint32_t hi, lo;
                size_t oA = (size_t)r0 * HID + gc0 + d;
                size_t oB = oA + 32;
                pack_hilo(x00 * cv00 - z00 * sv00, x01 * cv01 - z01 * sv01, hi, lo);
                *(uint32_t*)(qh + oA) = hi; *(uint32_t*)(ql + oA) = lo;
                pack_hilo(z00 * cv00 + x00 * sv00, z01 * cv01 + x01 * sv01, hi, lo);
                *(uint32_t*)(qh + oB) = hi; *(uint32_t*)(ql + oB) = lo;
                size_t oC = (size_t)r1 * HID + gc0 + d;
                size_t oD = oC + 32;
                pack_hilo(x10 * cv10 - z10 * sv10, x11 * cv11 - z11 * sv11, hi, lo);
                *(uint32_t*)(qh + oC) = hi; *(uint32_t*)(ql + oC) = lo;
                pack_hilo(z10 * cv10 + x10 * sv10, z11 * cv11 + x11 * sv11, hi, lo);
                *(uint32_t*)(qh + oD) = hi; *(uint32_t*)(ql + oD) = lo;
            }
        }
    } else if (gc0 < HID + KVDIM) {
        const int cb = gc0 - HID;
#pragma unroll
        for (int mt = 0; mt < 4; ++mt) {
            const int r0 = bm + wm * 64 + mt * 16 + er;
            const int r1 = r0 + 8;
            const int p0 = r0 & (S_LEN - 1), p1 = r1 & (S_LEN - 1);
#pragma unroll
            for (int nt = 0; nt < 4; ++nt) {
                const int d = nt * 8 + ec;
                float cv00 = rc[p0 * 32 + d],     sv00 = rs[p0 * 32 + d];
                float cv01 = rc[p0 * 32 + d + 1], sv01 = rs[p0 * 32 + d + 1];
                float cv10 = rc[p1 * 32 + d],     sv10 = rs[p1 * 32 + d];
                float cv11 = rc[p1 * 32 + d + 1], sv11 = rs[p1 * 32 + d + 1];
                float x00 = acc[mt][nt][0],     x01 = acc[mt][nt][1];
                float x10 = acc[mt][nt][2],     x11 = acc[mt][nt][3];
                float z00 = acc[mt][nt + 4][0], z01 = acc[mt][nt + 4][1];
                float z10 = acc[mt][nt + 4][2], z11 = acc[mt][nt + 4][3];
                __half2 v;
                v = __floats2half2_rn(x00 * cv00 - z00 * sv00, x01 * cv01 - z01 * sv01);
                *(__half2*)(k16 + (size_t)r0 * KVDIM + cb + d) = v;
                v = __floats2half2_rn(z00 * cv00 + x00 * sv00, z01 * cv01 + x01 * sv01);
                *(__half2*)(k16 + (size_t)r0 * KVDIM + cb + d + 32) = v;
                v = __floats2half2_rn(x10 * cv10 - z10 * sv10, x11 * cv11 - z11 * sv11);
                *(__half2*)(k16 + (size_t)r1 * KVDIM + cb + d) = v;
                v = __floats2half2_rn(z10 * cv10 + x10 * sv10, z11 * cv11 + x11 * sv11);
                *(__half2*)(k16 + (size_t)r1 * KVDIM + cb + d + 32) = v;
            }
        }
    } else {
        const int cb = gc0 - HID - KVDIM;
#pragma unroll
        for (int mt = 0; mt < 4; ++mt) {
            const int r0 = bm + wm * 64 + mt * 16 + er;
            const int r1 = r0 + 8;
#pragma unroll
            for (int nt = 0; nt < 8; ++nt) {
                const int d = nt * 8 + ec;
                __half2 v;
                v = __floats2half2_rn(acc[mt][nt][0], acc[mt][nt][1]);
                *(__half2*)(v16 + (size_t)r0 * KVDIM + cb + d) = v;
                v = __floats2half2_rn(acc[mt][nt][2], acc[mt][nt][3]);
                *(__half2*)(v16 + (size_t)r1 * KVDIM + cb + d) = v;
            }
        }
    }
}

// ============================================================================
// Tensor-core flash attention (fp16 2-term, fp32 accum, causal)
// Proven R9/R11 version — unchanged.
// ============================================================================
#define AT_ROWB 144
#define AT_TILE (64 * AT_ROWB)
#define AT_QTILE (128 * AT_ROWB)
#define ATTN_SMEM (2 * AT_QTILE + 4 * AT_TILE)   // 73728 B

__global__ __launch_bounds__(256) void attn_mma(
    const __half* __restrict__ qh, const __half* __restrict__ ql,
    const __half* __restrict__ k16, const __half* __restrict__ v16,
    __half* __restrict__ oh, __half* __restrict__ ol)
{
    extern __shared__ char smem[];
    const uint32_t sbase = smem_to_u32(smem);

    const int qt  = (int)(gridDim.x - 1 - blockIdx.x);   // heavy-first
    const int h   = blockIdx.y;
    const int b   = blockIdx.z;
    const int kvh = h >> 2;
    const int q0  = qt << 7;
    const int tid = threadIdx.x;
    const int warp = tid >> 5;
    const int lane = tid & 31;

    const uint32_t sQh = sbase;
    const uint32_t sQl = sbase + AT_QTILE;
    auto kvtile = [&](int buf, int t) -> uint32_t {
        return sbase + 2 * AT_QTILE + (buf * 2 + t) * AT_TILE;
    };

    {
        const int lrow = tid >> 1;
        const int lsg  = (tid & 1) * 4;
        const size_t grow = (size_t)(b * S_LEN + q0 + lrow) * HID + h * HDIM;
#pragma unroll
        for (int i = 0; i < 4; ++i) {
            int seg = lsg + i;
            uint32_t so = (uint32_t)(lrow * AT_ROWB + seg * 16);
            CP_ASYNC16(sQh + so, qh + grow + seg * 8);
            CP_ASYNC16(sQl + so, ql + grow + seg * 8);
        }
        CP_COMMIT();
    }

    const int krow = tid >> 2;
    const int ksg  = (tid & 3) * 2;
    auto issue_kv = [&](int kt, int buf) {
        const size_t grow = (size_t)(b * S_LEN + kt * 64 + krow) * KVDIM + kvh * HDIM;
        const uint32_t t0 = kvtile(buf, 0), t1 = kvtile(buf, 1);
#pragma unroll
        for (int i = 0; i < 2; ++i) {
            int seg = ksg + i;
            uint32_t so = (uint32_t)(krow * AT_ROWB + seg * 16);
            CP_ASYNC16(t0 + so, k16 + grow + seg * 8);
            CP_ASYNC16(t1 + so, v16 + grow + seg * 8);
        }
        CP_COMMIT();
    };

    issue_kv(0, 0);

    const uint32_t a_row  = (uint32_t)(warp * 16 + (lane & 15));
    const uint32_t a_colb = (uint32_t)((lane >> 4) * 16);
    const uint32_t kb_row = (uint32_t)(lane & 7);
    const uint32_t kb_sel = (uint32_t)(((lane >> 3) & 1) * 16);
    const uint32_t v_row  = (uint32_t)(lane & 15);

    const int er = lane >> 2;
    const int ec = (lane & 3) * 2;
    const int qg0 = q0 + warp * 16 + er;
    const int qg1 = qg0 + 8;

    uint32_t qhf[4][4], qlf[4][4];

    float o[8][4];
#pragma unroll
    for (int i = 0; i < 8; ++i)
#pragma unroll
        for (int c = 0; c < 4; ++c) o[i][c] = 0.f;
    float m0 = -INFINITY, m1 = -INFINITY, l0 = 0.f, l1 = 0.f;

    const int NT = 2 * qt + 2;

    for (int kt = 0; kt < NT; ++kt) {
        const int buf = kt & 1;
        if (kt + 1 < NT) { issue_kv(kt + 1, buf ^ 1); CP_WAIT(1); }
        else             { CP_WAIT(0); }
        __syncthreads();

        if (kt == 0) {
#pragma unroll
            for (int ks = 0; ks < 4; ++ks) {
                uint32_t off = a_row * AT_ROWB + a_colb + ks * 32;
                ldsm_x4(qhf[ks], sQh + off);
                ldsm_x4(qlf[ks], sQl + off);
            }
        }

        float s[8][4];
#pragma unroll
        for (int nt = 0; nt < 8; ++nt)
#pragma unroll
            for (int c = 0; c < 4; ++c) s[nt][c] = 0.f;

        const uint32_t sK = kvtile(buf, 0);
#pragma unroll
        for (int nt = 0; nt < 8; ++nt) {
#pragma unroll
            for (int ks = 0; ks < 4; ++ks) {
                uint32_t off = (nt * 8 + kb_row) * AT_ROWB + kb_sel + ks * 32;
                uint32_t kf[2];
                ldsm_x2(kf, sK + off);
                mma16816(s[nt], qhf[ks], kf);
                mma16816(s[nt], qlf[ks], kf);
            }
        }

        const int k0 = kt << 6;
#pragma unroll
        for (int nt = 0; nt < 8; ++nt)
#pragma unroll
            for (int c = 0; c < 4; ++c) s[nt][c] *= 0.125f;

        if (kt >= 2 * qt) {
#pragma unroll
            for (int nt = 0; nt < 8; ++nt) {
                int kg = k0 + nt * 8 + ec;
                if (kg     > qg0) s[nt][0] = -INFINITY;
                if (kg + 1 > qg0) s[nt][1] = -INFINITY;
                if (kg     > qg1) s[nt][2] = -INFINITY;
                if (kg + 1 > qg1) s[nt][3] = -INFINITY;
            }
        }

        float mx0 = -INFINITY, mx1 = -INFINITY;
#pragma unroll
        for (int nt = 0; nt < 8; ++nt) {
            mx0 = fmaxf(mx0, fmaxf(s[nt][0], s[nt][1]));
            mx1 = fmaxf(mx1, fmaxf(s[nt][2], s[nt][3]));
        }
        mx0 = fmaxf(mx0, __shfl_xor_sync(0xffffffffu, mx0, 1));
        mx0 = fmaxf(mx0, __shfl_xor_sync(0xffffffffu, mx0, 2));
        mx1 = fmaxf(mx1, __shfl_xor_sync(0xffffffffu, mx1, 1));
        mx1 = fmaxf(mx1, __shfl_xor_sync(0xffffffffu, mx1, 2));

        float mn0 = fmaxf(m0, mx0), mn1 = fmaxf(m1, mx1);
        float cr0 = __expf(m0 - mn0), cr1 = __expf(m1 - mn1);

        float ls0 = 0.f, ls1 = 0.f;
#pragma unroll
        for (int nt = 0; nt < 8; ++nt) {
            s[nt][0] = __expf(s[nt][0] - mn0);
            s[nt][1] = __expf(s[nt][1] - mn0);
            s[nt][2] = __expf(s[nt][2] - mn1);
            s[nt][3] = __expf(s[nt][3] - mn1);
            ls0 += s[nt][0] + s[nt][1];
            ls1 += s[nt][2] + s[nt][3];
        }
        ls0 += __shfl_xor_sync(0xffffffffu, ls0, 1);
        ls0 += __shfl_xor_sync(0xffffffffu, ls0, 2);
        ls1 += __shfl_xor_sync(0xffffffffu, ls1, 1);
        ls1 += __shfl_xor_sync(0xffffffffu, ls1, 2);
        l0 = l0 * cr0 + ls0;
        l1 = l1 * cr1 + ls1;
        m0 = mn0; m1 = mn1;

#pragma unroll
        for (int nt = 0; nt < 8; ++nt) {
            o[nt][0] *= cr0; o[nt][1] *= cr0;
            o[nt][2] *= cr1; o[nt][3] *= cr1;
        }

        uint32_t ph[4][4], pl[4][4];
#pragma unroll
        for (int ks = 0; ks < 4; ++ks) {
            pack_hilo(s[2 * ks][0],     s[2 * ks][1],     ph[ks][0], pl[ks][0]);
            pack_hilo(s[2 * ks][2],     s[2 * ks][3],     ph[ks][1], pl[ks][1]);
            pack_hilo(s[2 * ks + 1][0], s[2 * ks + 1][1], ph[ks][2], pl[ks][2]);
            pack_hilo(s[2 * ks + 1][2], s[2 * ks + 1][3], ph[ks][3], pl[ks][3]);
        }

        const uint32_t sV = kvtile(buf, 1);
#pragma unroll
        for (int nt = 0; nt < 8; ++nt) {
#pragma unroll
            for (int ks = 0; ks < 4; ++ks) {
                uint32_t off = (ks * 16 + v_row) * AT_ROWB + nt * 16;
                uint32_t vf[2];
                ldsm_x2_trans(vf, sV + off);
                mma16816(o[nt], ph[ks], vf);
                mma16816(o[nt], pl[ks], vf);
            }
        }
        __syncthreads();
    }

    const float il0 = 1.f / l0, il1 = 1.f / l1;
    const size_t row0 = (size_t)(b * S_LEN + qg0);
    const size_t row1 = (size_t)(b * S_LEN + qg1);
#pragma unroll
    for (int nt = 0; nt < 8; ++nt) {
        const int col = h * HDIM + nt * 8 + ec;
        uint32_t hi, lo;
        pack_hilo(o[nt][0] * il0, o[nt][1] * il0, hi, lo);
        *(uint32_t*)(oh + row0 * HID + col) = hi;
        *(uint32_t*)(ol + row0 * HID + col) = lo;
        pack_hilo(o[nt][2] * il1, o[nt][3] * il1, hi, lo);
        *(uint32_t*)(oh + row1 * HID + col) = hi;
        *(uint32_t*)(ol + row1 * HID + col) = lo;
    }
}

// ============================================================================
// kernel_launch
// ============================================================================
extern "C" void kernel_launch(void* const* d_in, const int* in_sizes, int n_in,
                              void* d_out, int out_size)
{
    (void)in_sizes; (void)n_in; (void)out_size;
    const float* x  = (const float*)d_in[0];
    const float* Wq = (const float*)d_in[1];
    const float* Wk = (const float*)d_in[2];
    const float* Wv = (const float*)d_in[3];
    const float* Wo = (const float*)d_in[4];
    float* out = (float*)d_out;

    float *rc, *rs;
    cudaGetSymbolAddress((void**)&rc, g_rc);
    cudaGetSymbolAddress((void**)&rs, g_rs);

    __half *xh, *xl, *w3, *wo, *ah, *al, *qhb, *qlb, *k16, *v16;
    cudaGetSymbolAddress((void**)&xh,  g_xh);
    cudaGetSymbolAddress((void**)&xl,  g_xl);
    cudaGetSymbolAddress((void**)&w3,  g_w3);
    cudaGetSymbolAddress((void**)&wo,  g_wo);
    cudaGetSymbolAddress((void**)&ah,  g_ah);
    cudaGetSymbolAddress((void**)&al,  g_al);
    cudaGetSymbolAddress((void**)&qhb, g_qh);
    cudaGetSymbolAddress((void**)&qlb, g_ql);
    cudaGetSymbolAddress((void**)&k16, g_k16);
    cudaGetSymbolAddress((void**)&v16, g_v16);

    cudaFuncSetAttribute(gemm_mma, cudaFuncAttributeMaxDynamicSharedMemorySize, GEMM_SMEM);
    cudaFuncSetAttribute(attn_mma, cudaFuncAttributeMaxDynamicSharedMemorySize, ATTN_SMEM);

    const int M = MROWS;
    const int nx = M * HID;
    const int nconv = (QKVN * HID + HID * HID) / 4;

    // rope tables
    rope_table<<<(S_LEN * 32 + 255) / 256, 256>>>(rc, rs);

    // x split
    split_fp16_v4<<<(nx / 4 + 255) / 256, 256>>>((const float4*)x, (uint2*)xh, (uint2*)xl, nx / 4);

    // all weight converts in one launch
    conv_weights_v4<<<(nconv + 255) / 256, 256>>>(
        (const float4*)Wq, (const float4*)Wk, (const float4*)Wv, (const float4*)Wo,
        (uint2*)w3, (uint2*)wo);

    // fused QKV projection with rope+fp16 epilogue (4 warps, 64x64 warp tile)
    gemm_mma<<<dim3(QKVN / BN, M / BM), 128, GEMM_SMEM>>>(
        xh, xl, w3, nullptr, M, QKVN, HID,
        1, rc, rs, qhb, qlb, k16, v16);

    // causal flash attention (heavy-first)
    attn_mma<<<dim3(S_LEN / 128, NHEADS, BATCH), 256, ATTN_SMEM>>>(
        qhb, qlb, k16, v16, ah, al);

    // output projection
    gemm_mma<<<dim3(HID / BN, M / BM), 128, GEMM_SMEM>>>(
        ah, al, wo, out, M, HID, HID,
        0, nullptr, nullptr, nullptr, nullptr, nullptr, nullptr);
}

// round 14
// speedup vs baseline: 1.3740x; 1.3740x over previous
#include <cuda_runtime.h>
#include <cuda_fp16.h>
#include <math.h>
#include <stdint.h>

#define S_LEN   2048
#define BATCH   2
#define HID     2048
#define NHEADS  32
#define KVHEADS 8
#define HDIM    64
#define MROWS   (BATCH * S_LEN)     // 4096
#define KVDIM   (KVHEADS * HDIM)    // 512
#define QKVN    (HID + 2 * KVDIM)   // 3072

// ---------------- scratch (static device globals; no allocations) ----------
__device__ __half g_xh [(size_t)MROWS * HID];
__device__ __half g_xl [(size_t)MROWS * HID];
__device__ __half g_w3 [(size_t)QKVN * HID];
__device__ __half g_wo [(size_t)HID * HID];
__device__ __half g_ah [(size_t)MROWS * HID];
__device__ __half g_al [(size_t)MROWS * HID];

__device__ __half g_qh [(size_t)MROWS * HID];
__device__ __half g_ql [(size_t)MROWS * HID];
__device__ __half g_k16[(size_t)MROWS * KVDIM];
__device__ __half g_v16[(size_t)MROWS * KVDIM];

__device__ float g_rc[S_LEN * 32];
__device__ float g_rs[S_LEN * 32];

// ============================================================================
// PTX helpers (plain sm_103-safe)
// ============================================================================
__device__ __forceinline__ uint32_t smem_to_u32(const void* p) {
    uint32_t a;
    asm("{ .reg .u64 t; cvta.to.shared.u64 t, %1; cvt.u32.u64 %0, t; }"
        : "=r"(a) : "l"(p));
    return a;
}

#define CP_ASYNC16(smem, gmem) \
    asm volatile("cp.async.cg.shared.global [%0], [%1], 16;" \
                 :: "r"(smem), "l"(gmem) : "memory")
#define CP_COMMIT() asm volatile("cp.async.commit_group;" ::: "memory")
#define CP_WAIT(n)  asm volatile("cp.async.wait_group %0;" :: "n"(n) : "memory")

__device__ __forceinline__ void ldsm_x4(uint32_t* r, uint32_t addr) {
    asm volatile("ldmatrix.sync.aligned.m8n8.x4.shared.b16 {%0,%1,%2,%3}, [%4];"
        : "=r"(r[0]), "=r"(r[1]), "=r"(r[2]), "=r"(r[3]) : "r"(addr));
}
__device__ __forceinline__ void ldsm_x2(uint32_t* r, uint32_t addr) {
    asm volatile("ldmatrix.sync.aligned.m8n8.x2.shared.b16 {%0,%1}, [%2];"
        : "=r"(r[0]), "=r"(r[1]) : "r"(addr));
}
__device__ __forceinline__ void ldsm_x2_trans(uint32_t* r, uint32_t addr) {
    asm volatile("ldmatrix.sync.aligned.m8n8.x2.trans.shared.b16 {%0,%1}, [%2];"
        : "=r"(r[0]), "=r"(r[1]) : "r"(addr));
}

__device__ __forceinline__ void mma16816(float* d, const uint32_t* a, const uint32_t* b) {
    asm volatile(
        "mma.sync.aligned.m16n8k16.row.col.f32.f16.f16.f32 "
        "{%0,%1,%2,%3}, {%4,%5,%6,%7}, {%8,%9}, {%0,%1,%2,%3};"
        : "+f"(d[0]), "+f"(d[1]), "+f"(d[2]), "+f"(d[3])
        : "r"(a[0]), "r"(a[1]), "r"(a[2]), "r"(a[3]), "r"(b[0]), "r"(b[1]));
}

__device__ __forceinline__ void pack_hilo(float a, float b, uint32_t& hi, uint32_t& lo) {
    __half ha = __float2half_rn(a);
    __half hb = __float2half_rn(b);
    __half2 H; H.x = ha; H.y = hb;
    hi = *reinterpret_cast<uint32_t*>(&H);
    __half2 L;
    L.x = __float2half_rn(a - __half2float(ha));
    L.y = __float2half_rn(b - __half2float(hb));
    lo = *reinterpret_cast<uint32_t*>(&L);
}

// ============================================================================
// vectorized fp32 -> fp16 split / convert
// ============================================================================
__global__ void split_fp16_v4(const float4* __restrict__ in,
                              uint2* __restrict__ hi, uint2* __restrict__ lo, int n4)
{
    int i = blockIdx.x * blockDim.x + threadIdx.x;
    if (i >= n4) return;
    float4 v = in[i];
    __half2 h0 = __floats2half2_rn(v.x, v.y);
    __half2 h1 = __floats2half2_rn(v.z, v.w);
    __half2 l0 = __floats2half2_rn(v.x - __low2float(h0),  v.y - __high2float(h0));
    __half2 l1 = __floats2half2_rn(v.z - __low2float(h1),  v.w - __high2float(h1));
    uint2 H = {*reinterpret_cast<uint32_t*>(&h0), *reinterpret_cast<uint32_t*>(&h1)};
    uint2 L = {*reinterpret_cast<uint32_t*>(&l0), *reinterpret_cast<uint32_t*>(&l1)};
    hi[i] = H;
    lo[i] = L;
}

// fused Wq|Wk|Wv -> w3  and  Wo -> wo  (one launch)
__global__ void conv_weights_v4(const float4* __restrict__ wq, const float4* __restrict__ wk,
                                const float4* __restrict__ wv, const float4* __restrict__ woin,
                                uint2* __restrict__ w3, uint2* __restrict__ wo)
{
    const int nq = HID * HID / 4;
    const int nk = KVDIM * HID / 4;
    const int n3 = nq + 2 * nk;
    const int tot = n3 + nq;
    int i = blockIdx.x * blockDim.x + threadIdx.x;
    if (i >= tot) return;
    float4 v;
    uint2* dst;
    int oi;
    if (i < nq)            { v = wq[i];            dst = w3; oi = i; }
    else if (i < nq + nk)  { v = wk[i - nq];       dst = w3; oi = i; }
    else if (i < n3)       { v = wv[i - nq - nk];  dst = w3; oi = i; }
    else                   { v = woin[i - n3];     dst = wo; oi = i - n3; }
    __half2 h0 = __floats2half2_rn(v.x, v.y);
    __half2 h1 = __floats2half2_rn(v.z, v.w);
    uint2 H = {*reinterpret_cast<uint32_t*>(&h0), *reinterpret_cast<uint32_t*>(&h1)};
    dst[oi] = H;
}

// ============================================================================
// RoPE table
// ============================================================================
__global__ void rope_table(float* __restrict__ ct, float* __restrict__ st)
{
    int t = blockIdx.x * blockDim.x + threadIdx.x;
    if (t >= S_LEN * 32) return;
    int pos  = t >> 5;
    int pair = t & 31;
    float inv = (float)exp(-(double)pair * (9.210340371976184 / 32.0));
    float a = (float)pos * inv;
    float s, c;
    sincosf(a, &s, &c);
    ct[t] = c;
    st[t] = s;
}

// ============================================================================
// fp16 2-term GEMM via mma.sync, 2-stage cp.async (61.4 KB -> 2 CTAs/SM),
// 4x2 warp grid (warp tile 32x64), 256 threads (R11 config = 16 warps/SM).
// MMA stream reordered: hi-sweep then lo-sweep (16 independent MMAs between
// same-accumulator reuse) to hide HMMA RAW latency. Per-acc op order
// unchanged (hi then lo) -> bit-identical results.
// ============================================================================
#define BM 128
#define BN 128
#define BK 32
#define ROWB   80
#define ASZ    (128 * ROWB)
#define STAGE  (3 * ASZ)                 // Ah, Al, B tiles
#define GEMM_SMEM (2 * STAGE)            // 61440 B -> 2 CTAs/SM

__global__ __launch_bounds__(256) void gemm_mma(
    const __half* __restrict__ Ah, const __half* __restrict__ Al,
    const __half* __restrict__ B,
    float* __restrict__ C, int M, int N, int K,
    int qkv_mode,
    const float* __restrict__ rc, const float* __restrict__ rs,
    __half* __restrict__ qh, __half* __restrict__ ql,
    __half* __restrict__ k16, __half* __restrict__ v16)
{
    extern __shared__ char smem[];
    const uint32_t sbase = smem_to_u32(smem);

    const int tid  = threadIdx.x;
    const int wid  = tid >> 5;
    const int lane = tid & 31;
    const int wm   = wid >> 1;        // 0..3 (row band)
    const int wn   = wid & 1;         // 0..1 (col band, 64 cols = one head)
    const int bm   = blockIdx.y * BM;
    const int bn   = blockIdx.x * BN;

    const __half* gAh = Ah + (size_t)bm * K;
    const __half* gAl = Al + (size_t)bm * K;
    const __half* gB  = B  + (size_t)bn * K;

    const int NC = K / BK;

    const int lr  = tid >> 2;
    const int lsg = tid & 3;
    auto issue = [&](int kc, int buf) {
        const uint32_t sb = sbase + buf * STAGE;
        const size_t kofs = (size_t)kc * BK + lsg * 8;
#pragma unroll
        for (int t = 0; t < 2; ++t) {
            int r = lr + t * 64;
            uint32_t so = (uint32_t)(r * ROWB + lsg * 16);
            size_t g = (size_t)r * K + kofs;
            CP_ASYNC16(sb + so,           gAh + g);
            CP_ASYNC16(sb + ASZ + so,     gAl + g);
            CP_ASYNC16(sb + 2 * ASZ + so, gB  + g);
        }
        CP_COMMIT();
    };

    float acc[2][8][4];
#pragma unroll
    for (int i = 0; i < 2; ++i)
#pragma unroll
        for (int j = 0; j < 8; ++j)
#pragma unroll
            for (int c = 0; c < 4; ++c) acc[i][j][c] = 0.f;

    const uint32_t a_row  = (uint32_t)(wm * 32 + (lane & 15));
    const uint32_t a_colb = (uint32_t)((lane >> 4) * 16);
    const uint32_t bp_row = (uint32_t)(wn * 64 + ((lane >> 4) << 3) + (lane & 7));
    const uint32_t bp_sel = (uint32_t)(((lane >> 3) & 1) * 16);

    issue(0, 0);
    issue(1, 1);

    for (int kt = 0; kt < NC; ++kt) {
        const int buf = kt & 1;
        if (kt + 2 <= NC) { CP_WAIT(1); }
        else              { CP_WAIT(0); }
        __syncthreads();

        const uint32_t sAh = sbase + buf * STAGE;
        const uint32_t sAl = sAh + ASZ;
        const uint32_t sB  = sAh + 2 * ASZ;

#pragma unroll
        for (int ks = 0; ks < 2; ++ks) {
            const uint32_t kofs = ks * 32;

            uint32_t ah[2][4], al[2][4], bb[4][4];
#pragma unroll
            for (int mt = 0; mt < 2; ++mt) {
                uint32_t off = (a_row + mt * 16) * ROWB + a_colb + kofs;
                ldsm_x4(ah[mt], sAh + off);
                ldsm_x4(al[mt], sAl + off);
            }
#pragma unroll
            for (int ntp = 0; ntp < 4; ++ntp) {
                uint32_t off = (bp_row + ntp * 16) * ROWB + bp_sel + kofs;
                ldsm_x4(bb[ntp], sB + off);
            }
            // hi sweep: 16 independent MMAs
#pragma unroll
            for (int mt = 0; mt < 2; ++mt)
#pragma unroll
                for (int nt = 0; nt < 8; ++nt) {
                    const uint32_t* bf = &bb[nt >> 1][(nt & 1) * 2];
                    mma16816(acc[mt][nt], ah[mt], bf);
                }
            // lo sweep: each dep is 16 MMA slots behind its hi
#pragma unroll
            for (int mt = 0; mt < 2; ++mt)
#pragma unroll
                for (int nt = 0; nt < 8; ++nt) {
                    const uint32_t* bf = &bb[nt >> 1][(nt & 1) * 2];
                    mma16816(acc[mt][nt], al[mt], bf);
                }
        }
        __syncthreads();

        if (kt + 2 < NC) issue(kt + 2, buf);
    }

    const int er = lane >> 2;
    const int ec = (lane & 3) * 2;

    if (!qkv_mode) {
#pragma unroll
        for (int mt = 0; mt < 2; ++mt) {
            const int row0 = bm + wm * 32 + mt * 16 + er;
#pragma unroll
            for (int nt = 0; nt < 8; ++nt) {
                const int col = bn + wn * 64 + nt * 8 + ec;
                float2 v0 = {acc[mt][nt][0], acc[mt][nt][1]};
                float2 v1 = {acc[mt][nt][2], acc[mt][nt][3]};
                *(float2*)(C + (size_t)row0 * N + col)       = v0;
                *(float2*)(C + (size_t)(row0 + 8) * N + col) = v1;
            }
        }
        return;
    }

    // ---- fused QKV epilogue: rope + fp16 conversion ----
    const int gc0 = bn + wn * 64;

    if (gc0 < HID) {
#pragma unroll
        for (int mt = 0; mt < 2; ++mt) {
            const int r0 = bm + wm * 32 + mt * 16 + er;
            const int r1 = r0 + 8;
            const int p0 = r0 & (S_LEN - 1), p1 = r1 & (S_LEN - 1);
#pragma unroll
            for (int nt = 0; nt < 4; ++nt) {
                const int d = nt * 8 + ec;
                float cv00 = rc[p0 * 32 + d],     sv00 = rs[p0 * 32 + d];
                float cv01 = rc[p0 * 32 + d + 1], sv01 = rs[p0 * 32 + d + 1];
                float cv10 = rc[p1 * 32 + d],     sv10 = rs[p1 * 32 + d];
                float cv11 = rc[p1 * 32 + d + 1], sv11 = rs[p1 * 32 + d + 1];
                float x00 = acc[mt][nt][0],     x01 = acc[mt][nt][1];
                float x10 = acc[mt][nt][2],     x11 = acc[mt][nt][3];
                float z00 = acc[mt][nt + 4][0], z01 = acc[mt][nt + 4][1];
                float z10 = acc[mt][nt + 4][2], z11 = acc[mt][nt + 4][3];
                uint32_t hi, lo;
                size_t oA = (size_t)r0 * HID + gc0 + d;
                size_t oB = oA + 32;
                pack_hilo(x00 * cv00 - z00 * sv00, x01 * cv01 - z01 * sv01, hi, lo);
                *(uint32_t*)(qh + oA) = hi; *(uint32_t*)(ql + oA) = lo;
                pack_hilo(z00 * cv00 + x00 * sv00, z01 * cv01 + x01 * sv01, hi, lo);
                *(uint32_t*)(qh + oB) = hi; *(uint32_t*)(ql + oB) = lo;
                size_t oC = (size_t)r1 * HID + gc0 + d;
                size_t oD = oC + 32;
                pack_hilo(x10 * cv10 - z10 * sv10, x11 * cv11 - z11 * sv11, hi, lo);
                *(uint32_t*)(qh + oC) = hi; *(uint32_t*)(ql + oC) = lo;
                pack_hilo(z10 * cv10 + x10 * sv10, z11 * cv11 + x11 * sv11, hi, lo);
                *(uint32_t*)(qh + oD) = hi; *(uint32_t*)(ql + oD) = lo;
            }
        }
    } else if (gc0 < HID + KVDIM) {
        const int cb = gc0 - HID;
#pragma unroll
        for (int mt = 0; mt < 2; ++mt) {
            const int r0 = bm + wm * 32 + mt * 16 + er;
            const int r1 = r0 + 8;
            const int p0 = r0 & (S_LEN - 1), p1 = r1 & (S_LEN - 1);
#pragma unroll
            for (int nt = 0; nt < 4; ++nt) {
                const int d = nt * 8 + ec;
                float cv00 = rc[p0 * 32 + d],     sv00 = rs[p0 * 32 + d];
                float cv01 = rc[p0 * 32 + d + 1], sv01 = rs[p0 * 32 + d + 1];
                float cv10 = rc[p1 * 32 + d],     sv10 = rs[p1 * 32 + d];
                float cv11 = rc[p1 * 32 + d + 1], sv11 = rs[p1 * 32 + d + 1];
                float x00 = acc[mt][nt][0],     x01 = acc[mt][nt][1];
                float x10 = acc[mt][nt][2],     x11 = acc[mt][nt][3];
                float z00 = acc[mt][nt + 4][0], z01 = acc[mt][nt + 4][1];
                float z10 = acc[mt][nt + 4][2], z11 = acc[mt][nt + 4][3];
                __half2 v;
                v = __floats2half2_rn(x00 * cv00 - z00 * sv00, x01 * cv01 - z01 * sv01);
                *(__half2*)(k16 + (size_t)r0 * KVDIM + cb + d) = v;
                v = __floats2half2_rn(z00 * cv00 + x00 * sv00, z01 * cv01 + x01 * sv01);
                *(__half2*)(k16 + (size_t)r0 * KVDIM + cb + d + 32) = v;
                v = __floats2half2_rn(x10 * cv10 - z10 * sv10, x11 * cv11 - z11 * sv11);
                *(__half2*)(k16 + (size_t)r1 * KVDIM + cb + d) = v;
                v = __floats2half2_rn(z10 * cv10 + x10 * sv10, z11 * cv11 + x11 * sv11);
                *(__half2*)(k16 + (size_t)r1 * KVDIM + cb + d + 32) = v;
            }
        }
    } else {
        const int cb = gc0 - HID - KVDIM;
#pragma unroll
        for (int mt = 0; mt < 2; ++mt) {
            const int r0 = bm + wm * 32 + mt * 16 + er;
            const int r1 = r0 + 8;
#pragma unroll
            for (int nt = 0; nt < 8; ++nt) {
                const int d = nt * 8 + ec;
                __half2 v;
                v = __floats2half2_rn(acc[mt][nt][0], acc[mt][nt][1]);
                *(__half2*)(v16 + (size_t)r0 * KVDIM + cb + d) = v;
                v = __floats2half2_rn(acc[mt][nt][2], acc[mt][nt][3]);
                *(__half2*)(v16 + (size_t)r1 * KVDIM + cb + d) = v;
            }
        }
    }
}

// ============================================================================
// Tensor-core flash attention (fp16 2-term, fp32 accum, causal)
// R11 structure; MMA streams reordered hi-sweep/lo-sweep (ks-outer with
// fragment preload) — per-accumulator op order unchanged -> bit-identical.
// ============================================================================
#define AT_ROWB 144
#define AT_TILE (64 * AT_ROWB)
#define AT_QTILE (128 * AT_ROWB)
#define ATTN_SMEM (2 * AT_QTILE + 4 * AT_TILE)   // 73728 B

__global__ __launch_bounds__(256) void attn_mma(
    const __half* __restrict__ qh, const __half* __restrict__ ql,
    const __half* __restrict__ k16, const __half* __restrict__ v16,
    __half* __restrict__ oh, __half* __restrict__ ol)
{
    extern __shared__ char smem[];
    const uint32_t sbase = smem_to_u32(smem);

    const int qt  = (int)(gridDim.x - 1 - blockIdx.x);   // heavy-first
    const int h   = blockIdx.y;
    const int b   = blockIdx.z;
    const int kvh = h >> 2;
    const int q0  = qt << 7;
    const int tid = threadIdx.x;
    const int warp = tid >> 5;
    const int lane = tid & 31;

    const uint32_t sQh = sbase;
    const uint32_t sQl = sbase + AT_QTILE;
    auto kvtile = [&](int buf, int t) -> uint32_t {
        return sbase + 2 * AT_QTILE + (buf * 2 + t) * AT_TILE;
    };

    {
        const int lrow = tid >> 1;
        const int lsg  = (tid & 1) * 4;
        const size_t grow = (size_t)(b * S_LEN + q0 + lrow) * HID + h * HDIM;
#pragma unroll
        for (int i = 0; i < 4; ++i) {
            int seg = lsg + i;
            uint32_t so = (uint32_t)(lrow * AT_ROWB + seg * 16);
            CP_ASYNC16(sQh + so, qh + grow + seg * 8);
            CP_ASYNC16(sQl + so, ql + grow + seg * 8);
        }
        CP_COMMIT();
    }

    const int krow = tid >> 2;
    const int ksg  = (tid & 3) * 2;
    auto issue_kv = [&](int kt, int buf) {
        const size_t grow = (size_t)(b * S_LEN + kt * 64 + krow) * KVDIM + kvh * HDIM;
        const uint32_t t0 = kvtile(buf, 0), t1 = kvtile(buf, 1);
#pragma unroll
        for (int i = 0; i < 2; ++i) {
            int seg = ksg + i;
            uint32_t so = (uint32_t)(krow * AT_ROWB + seg * 16);
            CP_ASYNC16(t0 + so, k16 + grow + seg * 8);
            CP_ASYNC16(t1 + so, v16 + grow + seg * 8);
        }
        CP_COMMIT();
    };

    issue_kv(0, 0);

    const uint32_t a_row  = (uint32_t)(warp * 16 + (lane & 15));
    const uint32_t a_colb = (uint32_t)((lane >> 4) * 16);
    const uint32_t kb_row = (uint32_t)(lane & 7);
    const uint32_t kb_sel = (uint32_t)(((lane >> 3) & 1) * 16);
    const uint32_t v_row  = (uint32_t)(lane & 15);

    const int er = lane >> 2;
    const int ec = (lane & 3) * 2;
    const int qg0 = q0 + warp * 16 + er;
    const int qg1 = qg0 + 8;

    uint32_t qhf[4][4], qlf[4][4];

    float o[8][4];
#pragma unroll
    for (int i = 0; i < 8; ++i)
#pragma unroll
        for (int c = 0; c < 4; ++c) o[i][c] = 0.f;
    float m0 = -INFINITY, m1 = -INFINITY, l0 = 0.f, l1 = 0.f;

    const int NT = 2 * qt + 2;

    for (int kt = 0; kt < NT; ++kt) {
        const int buf = kt & 1;
        if (kt + 1 < NT) { issue_kv(kt + 1, buf ^ 1); CP_WAIT(1); }
        else             { CP_WAIT(0); }
        __syncthreads();

        if (kt == 0) {
#pragma unroll
            for (int ks = 0; ks < 4; ++ks) {
                uint32_t off = a_row * AT_ROWB + a_colb + ks * 32;
                ldsm_x4(qhf[ks], sQh + off);
                ldsm_x4(qlf[ks], sQl + off);
            }
        }

        // ---- S = Q K^T (2-term), ks-outer with hi/lo sweeps ----
        float s[8][4];
#pragma unroll
        for (int nt = 0; nt < 8; ++nt)
#pragma unroll
            for (int c = 0; c < 4; ++c) s[nt][c] = 0.f;

        const uint32_t sK = kvtile(buf, 0);
#pragma unroll
        for (int ks = 0; ks < 4; ++ks) {
            uint32_t kf[8][2];
#pragma unroll
            for (int nt = 0; nt < 8; ++nt)
                ldsm_x2(kf[nt], sK + (nt * 8 + kb_row) * AT_ROWB + kb_sel + ks * 32);
#pragma unroll
            for (int nt = 0; nt < 8; ++nt)
                mma16816(s[nt], qhf[ks], kf[nt]);
#pragma unroll
            for (int nt = 0; nt < 8; ++nt)
                mma16816(s[nt], qlf[ks], kf[nt]);
        }

        const int k0 = kt << 6;
#pragma unroll
        for (int nt = 0; nt < 8; ++nt)
#pragma unroll
            for (int c = 0; c < 4; ++c) s[nt][c] *= 0.125f;

        if (kt >= 2 * qt) {
#pragma unroll
            for (int nt = 0; nt < 8; ++nt) {
                int kg = k0 + nt * 8 + ec;
                if (kg     > qg0) s[nt][0] = -INFINITY;
                if (kg + 1 > qg0) s[nt][1] = -INFINITY;
                if (kg     > qg1) s[nt][2] = -INFINITY;
                if (kg + 1 > qg1) s[nt][3] = -INFINITY;
            }
        }

        // ---- online softmax ----
        float mx0 = -INFINITY, mx1 = -INFINITY;
#pragma unroll
        for (int nt = 0; nt < 8; ++nt) {
            mx0 = fmaxf(mx0, fmaxf(s[nt][0], s[nt][1]));
            mx1 = fmaxf(mx1, fmaxf(s[nt][2], s[nt][3]));
        }
        mx0 = fmaxf(mx0, __shfl_xor_sync(0xffffffffu, mx0, 1));
        mx0 = fmaxf(mx0, __shfl_xor_sync(0xffffffffu, mx0, 2));
        mx1 = fmaxf(mx1, __shfl_xor_sync(0xffffffffu, mx1, 1));
        mx1 = fmaxf(mx1, __shfl_xor_sync(0xffffffffu, mx1, 2));

        float mn0 = fmaxf(m0, mx0), mn1 = fmaxf(m1, mx1);
        float cr0 = __expf(m0 - mn0), cr1 = __expf(m1 - mn1);

        float ls0 = 0.f, ls1 = 0.f;
#pragma unroll
        for (int nt = 0; nt < 8; ++nt) {
            s[nt][0] = __expf(s[nt][0] - mn0);
            s[nt][1] = __expf(s[nt][1] - mn0);
            s[nt][2] = __expf(s[nt][2] - mn1);
            s[nt][3] = __expf(s[nt][3] - mn1);
            ls0 += s[nt][0] + s[nt][1];
            ls1 += s[nt][2] + s[nt][3];
        }
        ls0 += __shfl_xor_sync(0xffffffffu, ls0, 1);
        ls0 += __shfl_xor_sync(0xffffffffu, ls0, 2);
        ls1 += __shfl_xor_sync(0xffffffffu, ls1, 1);
        ls1 += __shfl_xor_sync(0xffffffffu, ls1, 2);
        l0 = l0 * cr0 + ls0;
        l1 = l1 * cr1 + ls1;
        m0 = mn0; m1 = mn1;

#pragma unroll
        for (int nt = 0; nt < 8; ++nt) {
            o[nt][0] *= cr0; o[nt][1] *= cr0;
            o[nt][2] *= cr1; o[nt][3] *= cr1;
        }

        // ---- pack P -> fp16 hi/lo fragments ----
        uint32_t ph[4][4], pl[4][4];
#pragma unroll
        for (int ks = 0; ks < 4; ++ks) {
            pack_hilo(s[2 * ks][0],     s[2 * ks][1],     ph[ks][0], pl[ks][0]);
            pack_hilo(s[2 * ks][2],     s[2 * ks][3],     ph[ks][1], pl[ks][1]);
            pack_hilo(s[2 * ks + 1][0], s[2 * ks + 1][1], ph[ks][2], pl[ks][2]);
            pack_hilo(s[2 * ks + 1][2], s[2 * ks + 1][3], ph[ks][3], pl[ks][3]);
        }

        // ---- O += P V (2-term), ks-outer with hi/lo sweeps ----
        const uint32_t sV = kvtile(buf, 1);
#pragma unroll
        for (int ks = 0; ks < 4; ++ks) {
            uint32_t vf[8][2];
#pragma unroll
            for (int nt = 0; nt < 8; ++nt)
                ldsm_x2_trans(vf[nt], sV + (ks * 16 + v_row) * AT_ROWB + nt * 16);
#pragma unroll
            for (int nt = 0; nt < 8; ++nt)
                mma16816(o[nt], ph[ks], vf[nt]);
#pragma unroll
            for (int nt = 0; nt < 8; ++nt)
                mma16816(o[nt], pl[ks], vf[nt]);
        }
        __syncthreads();
    }

    const float il0 = 1.f / l0, il1 = 1.f / l1;
    const size_t row0 = (size_t)(b * S_LEN + qg0);
    const size_t row1 = (size_t)(b * S_LEN + qg1);
#pragma unroll
    for (int nt = 0; nt < 8; ++nt) {
        const int col = h * HDIM + nt * 8 + ec;
        uint32_t hi, lo;
        pack_hilo(o[nt][0] * il0, o[nt][1] * il0, hi, lo);
        *(uint32_t*)(oh + row0 * HID + col) = hi;
        *(uint32_t*)(ol + row0 * HID + col) = lo;
        pack_hilo(o[nt][2] * il1, o[nt][3] * il1, hi, lo);
        *(uint32_t*)(oh + row1 * HID + col) = hi;
        *(uint32_t*)(ol + row1 * HID + col) = lo;
    }
}

// ============================================================================
// kernel_launch
// ============================================================================
extern "C" void kernel_launch(void* const* d_in, const int* in_sizes, int n_in,
                              void* d_out, int out_size)
{
    (void)in_sizes; (void)n_in; (void)out_size;
    const float* x  = (const float*)d_in[0];
    const float* Wq = (const float*)d_in[1];
    const float* Wk = (const float*)d_in[2];
    const float* Wv = (const float*)d_in[3];
    const float* Wo = (const float*)d_in[4];
    float* out = (float*)d_out;

    float *rc, *rs;
    cudaGetSymbolAddress((void**)&rc, g_rc);
    cudaGetSymbolAddress((void**)&rs, g_rs);

    __half *xh, *xl, *w3, *wo, *ah, *al, *qhb, *qlb, *k16, *v16;
    cudaGetSymbolAddress((void**)&xh,  g_xh);
    cudaGetSymbolAddress((void**)&xl,  g_xl);
    cudaGetSymbolAddress((void**)&w3,  g_w3);
    cudaGetSymbolAddress((void**)&wo,  g_wo);
    cudaGetSymbolAddress((void**)&ah,  g_ah);
    cudaGetSymbolAddress((void**)&al,  g_al);
    cudaGetSymbolAddress((void**)&qhb, g_qh);
    cudaGetSymbolAddress((void**)&qlb, g_ql);
    cudaGetSymbolAddress((void**)&k16, g_k16);
    cudaGetSymbolAddress((void**)&v16, g_v16);

    cudaFuncSetAttribute(gemm_mma, cudaFuncAttributeMaxDynamicSharedMemorySize, GEMM_SMEM);
    cudaFuncSetAttribute(attn_mma, cudaFuncAttributeMaxDynamicSharedMemorySize, ATTN_SMEM);

    const int M = MROWS;
    const int nx = M * HID;
    const int nconv = (QKVN * HID + HID * HID) / 4;

    // rope tables
    rope_table<<<(S_LEN * 32 + 255) / 256, 256>>>(rc, rs);

    // x split
    split_fp16_v4<<<(nx / 4 + 255) / 256, 256>>>((const float4*)x, (uint2*)xh, (uint2*)xl, nx / 4);

    // all weight converts in one launch
    conv_weights_v4<<<(nconv + 255) / 256, 256>>>(
        (const float4*)Wq, (const float4*)Wk, (const float4*)Wv, (const float4*)Wo,
        (uint2*)w3, (uint2*)wo);

    // fused QKV projection with rope+fp16 epilogue
    gemm_mma<<<dim3(QKVN / BN, M / BM), 256, GEMM_SMEM>>>(
        xh, xl, w3, nullptr, M, QKVN, HID,
        1, rc, rs, qhb, qlb, k16, v16);

    // causal flash attention (heavy-first)
    attn_mma<<<dim3(S_LEN / 128, NHEADS, BATCH), 256, ATTN_SMEM>>>(
        qhb, qlb, k16, v16, ah, al);

    // output projection
    gemm_mma<<<dim3(HID / BN, M / BM), 256, GEMM_SMEM>>>(
        ah, al, wo, out, M, HID, HID,
        0, nullptr, nullptr, nullptr, nullptr, nullptr, nullptr);
}

// round 15
// speedup vs baseline: 1.4961x; 1.0888x over previous
#include <cuda_runtime.h>
#include <cuda_fp16.h>
#include <math.h>
#include <stdint.h>

#define S_LEN   2048
#define BATCH   2
#define HID     2048
#define NHEADS  32
#define KVHEADS 8
#define HDIM    64
#define MROWS   (BATCH * S_LEN)     // 4096
#define KVDIM   (KVHEADS * HDIM)    // 512
#define QKVN    (HID + 2 * KVDIM)   // 3072

// ---------------- scratch (static device globals; no allocations) ----------
__device__ __half g_xh [(size_t)MROWS * HID];
__device__ __half g_xl [(size_t)MROWS * HID];
__device__ __half g_w3 [(size_t)QKVN * HID];
__device__ __half g_wo [(size_t)HID * HID];
__device__ __half g_a16[(size_t)MROWS * HID];      // attention out (single fp16)

__device__ __half g_qh [(size_t)MROWS * HID];
__device__ __half g_ql [(size_t)MROWS * HID];
__device__ __half g_k16[(size_t)MROWS * KVDIM];
__device__ __half g_v16[(size_t)MROWS * KVDIM];

__device__ float g_rc[S_LEN * 32];
__device__ float g_rs[S_LEN * 32];

// ============================================================================
// PTX helpers (plain sm_103-safe)
// ============================================================================
__device__ __forceinline__ uint32_t smem_to_u32(const void* p) {
    uint32_t a;
    asm("{ .reg .u64 t; cvta.to.shared.u64 t, %1; cvt.u32.u64 %0, t; }"
        : "=r"(a) : "l"(p));
    return a;
}

#define CP_ASYNC16(smem, gmem) \
    asm volatile("cp.async.cg.shared.global [%0], [%1], 16;" \
                 :: "r"(smem), "l"(gmem) : "memory")
#define CP_COMMIT() asm volatile("cp.async.commit_group;" ::: "memory")
#define CP_WAIT(n)  asm volatile("cp.async.wait_group %0;" :: "n"(n) : "memory")

__device__ __forceinline__ void ldsm_x4(uint32_t* r, uint32_t addr) {
    asm volatile("ldmatrix.sync.aligned.m8n8.x4.shared.b16 {%0,%1,%2,%3}, [%4];"
        : "=r"(r[0]), "=r"(r[1]), "=r"(r[2]), "=r"(r[3]) : "r"(addr));
}
__device__ __forceinline__ void ldsm_x2(uint32_t* r, uint32_t addr) {
    asm volatile("ldmatrix.sync.aligned.m8n8.x2.shared.b16 {%0,%1}, [%2];"
        : "=r"(r[0]), "=r"(r[1]) : "r"(addr));
}
__device__ __forceinline__ void ldsm_x2_trans(uint32_t* r, uint32_t addr) {
    asm volatile("ldmatrix.sync.aligned.m8n8.x2.trans.shared.b16 {%0,%1}, [%2];"
        : "=r"(r[0]), "=r"(r[1]) : "r"(addr));
}

__device__ __forceinline__ void mma16816(float* d, const uint32_t* a, const uint32_t* b) {
    asm volatile(
        "mma.sync.aligned.m16n8k16.row.col.f32.f16.f16.f32 "
        "{%0,%1,%2,%3}, {%4,%5,%6,%7}, {%8,%9}, {%0,%1,%2,%3};"
        : "+f"(d[0]), "+f"(d[1]), "+f"(d[2]), "+f"(d[3])
        : "r"(a[0]), "r"(a[1]), "r"(a[2]), "r"(a[3]), "r"(b[0]), "r"(b[1]));
}

__device__ __forceinline__ void pack_hilo(float a, float b, uint32_t& hi, uint32_t& lo) {
    __half ha = __float2half_rn(a);
    __half hb = __float2half_rn(b);
    __half2 H; H.x = ha; H.y = hb;
    hi = *reinterpret_cast<uint32_t*>(&H);
    __half2 L;
    L.x = __float2half_rn(a - __half2float(ha));
    L.y = __float2half_rn(b - __half2float(hb));
    lo = *reinterpret_cast<uint32_t*>(&L);
}

// ============================================================================
// vectorized fp32 -> fp16 split / convert
// ============================================================================
__global__ void split_fp16_v4(const float4* __restrict__ in,
                              uint2* __restrict__ hi, uint2* __restrict__ lo, int n4)
{
    int i = blockIdx.x * blockDim.x + threadIdx.x;
    if (i >= n4) return;
    float4 v = in[i];
    __half2 h0 = __floats2half2_rn(v.x, v.y);
    __half2 h1 = __floats2half2_rn(v.z, v.w);
    __half2 l0 = __floats2half2_rn(v.x - __low2float(h0),  v.y - __high2float(h0));
    __half2 l1 = __floats2half2_rn(v.z - __low2float(h1),  v.w - __high2float(h1));
    uint2 H = {*reinterpret_cast<uint32_t*>(&h0), *reinterpret_cast<uint32_t*>(&h1)};
    uint2 L = {*reinterpret_cast<uint32_t*>(&l0), *reinterpret_cast<uint32_t*>(&l1)};
    hi[i] = H;
    lo[i] = L;
}

// fused Wq|Wk|Wv -> w3  and  Wo -> wo  (one launch)
__global__ void conv_weights_v4(const float4* __restrict__ wq, const float4* __restrict__ wk,
                                const float4* __restrict__ wv, const float4* __restrict__ woin,
                                uint2* __restrict__ w3, uint2* __restrict__ wo)
{
    const int nq = HID * HID / 4;
    const int nk = KVDIM * HID / 4;
    const int n3 = nq + 2 * nk;
    const int tot = n3 + nq;
    int i = blockIdx.x * blockDim.x + threadIdx.x;
    if (i >= tot) return;
    float4 v;
    uint2* dst;
    int oi;
    if (i < nq)            { v = wq[i];            dst = w3; oi = i; }
    else if (i < nq + nk)  { v = wk[i - nq];       dst = w3; oi = i; }
    else if (i < n3)       { v = wv[i - nq - nk];  dst = w3; oi = i; }
    else                   { v = woin[i - n3];     dst = wo; oi = i - n3; }
    __half2 h0 = __floats2half2_rn(v.x, v.y);
    __half2 h1 = __floats2half2_rn(v.z, v.w);
    uint2 H = {*reinterpret_cast<uint32_t*>(&h0), *reinterpret_cast<uint32_t*>(&h1)};
    dst[oi] = H;
}

// ============================================================================
// RoPE table
// ============================================================================
__global__ void rope_table(float* __restrict__ ct, float* __restrict__ st)
{
    int t = blockIdx.x * blockDim.x + threadIdx.x;
    if (t >= S_LEN * 32) return;
    int pos  = t >> 5;
    int pair = t & 31;
    float inv = (float)exp(-(double)pair * (9.210340371976184 / 32.0));
    float a = (float)pos * inv;
    float s, c;
    sincosf(a, &s, &c);
    ct[t] = c;
    st[t] = s;
}

// ============================================================================
// fp16 GEMM via mma.sync, 2-stage cp.async (61.4 KB -> 2 CTAs/SM),
// 4x2 warp grid (warp tile 32x64), 256 threads.
// two_term=1: A = Ah + Al (2 MMA streams). two_term=0: A = Ah only.
// ============================================================================
#define BM 128
#define BN 128
#define BK 32
#define ROWB   80
#define ASZ    (128 * ROWB)
#define STAGE  (3 * ASZ)                 // Ah, Al, B tile slots
#define GEMM_SMEM (2 * STAGE)            // 61440 B -> 2 CTAs/SM

__global__ __launch_bounds__(256) void gemm_mma(
    const __half* __restrict__ Ah, const __half* __restrict__ Al,
    const __half* __restrict__ B,
    float* __restrict__ C, int M, int N, int K,
    int two_term, int qkv_mode,
    const float* __restrict__ rc, const float* __restrict__ rs,
    __half* __restrict__ qh, __half* __restrict__ ql,
    __half* __restrict__ k16, __half* __restrict__ v16)
{
    extern __shared__ char smem[];
    const uint32_t sbase = smem_to_u32(smem);

    const int tid  = threadIdx.x;
    const int wid  = tid >> 5;
    const int lane = tid & 31;
    const int wm   = wid >> 1;        // 0..3 (row band)
    const int wn   = wid & 1;         // 0..1 (col band, 64 cols = one head)
    const int bm   = blockIdx.y * BM;
    const int bn   = blockIdx.x * BN;

    const __half* gAh = Ah + (size_t)bm * K;
    const __half* gAl = two_term ? (Al + (size_t)bm * K) : gAh;
    const __half* gB  = B  + (size_t)bn * K;

    const int NC = K / BK;

    const int lr  = tid >> 2;
    const int lsg = tid & 3;
    auto issue = [&](int kc, int buf) {
        const uint32_t sb = sbase + buf * STAGE;
        const size_t kofs = (size_t)kc * BK + lsg * 8;
#pragma unroll
        for (int t = 0; t < 2; ++t) {
            int r = lr + t * 64;
            uint32_t so = (uint32_t)(r * ROWB + lsg * 16);
            size_t g = (size_t)r * K + kofs;
            CP_ASYNC16(sb + so,           gAh + g);
            if (two_term) CP_ASYNC16(sb + ASZ + so, gAl + g);
            CP_ASYNC16(sb + 2 * ASZ + so, gB  + g);
        }
        CP_COMMIT();
    };

    float acc[2][8][4];
#pragma unroll
    for (int i = 0; i < 2; ++i)
#pragma unroll
        for (int j = 0; j < 8; ++j)
#pragma unroll
            for (int c = 0; c < 4; ++c) acc[i][j][c] = 0.f;

    const uint32_t a_row  = (uint32_t)(wm * 32 + (lane & 15));
    const uint32_t a_colb = (uint32_t)((lane >> 4) * 16);
    const uint32_t bp_row = (uint32_t)(wn * 64 + ((lane >> 4) << 3) + (lane & 7));
    const uint32_t bp_sel = (uint32_t)(((lane >> 3) & 1) * 16);

    issue(0, 0);
    issue(1, 1);

    for (int kt = 0; kt < NC; ++kt) {
        const int buf = kt & 1;
        if (kt + 2 <= NC) { CP_WAIT(1); }
        else              { CP_WAIT(0); }
        __syncthreads();

        const uint32_t sAh = sbase + buf * STAGE;
        const uint32_t sAl = sAh + ASZ;
        const uint32_t sB  = sAh + 2 * ASZ;

#pragma unroll
        for (int ks = 0; ks < 2; ++ks) {
            const uint32_t kofs = ks * 32;

            uint32_t ah[2][4], al[2][4], bb[4][4];
#pragma unroll
            for (int mt = 0; mt < 2; ++mt) {
                uint32_t off = (a_row + mt * 16) * ROWB + a_colb + kofs;
                ldsm_x4(ah[mt], sAh + off);
                if (two_term) ldsm_x4(al[mt], sAl + off);
            }
#pragma unroll
            for (int ntp = 0; ntp < 4; ++ntp) {
                uint32_t off = (bp_row + ntp * 16) * ROWB + bp_sel + kofs;
                ldsm_x4(bb[ntp], sB + off);
            }
            // hi sweep
#pragma unroll
            for (int mt = 0; mt < 2; ++mt)
#pragma unroll
                for (int nt = 0; nt < 8; ++nt) {
                    const uint32_t* bf = &bb[nt >> 1][(nt & 1) * 2];
                    mma16816(acc[mt][nt], ah[mt], bf);
                }
            // lo sweep (2-term only)
            if (two_term) {
#pragma unroll
                for (int mt = 0; mt < 2; ++mt)
#pragma unroll
                    for (int nt = 0; nt < 8; ++nt) {
                        const uint32_t* bf = &bb[nt >> 1][(nt & 1) * 2];
                        mma16816(acc[mt][nt], al[mt], bf);
                    }
            }
        }
        __syncthreads();

        if (kt + 2 < NC) issue(kt + 2, buf);
    }

    const int er = lane >> 2;
    const int ec = (lane & 3) * 2;

    if (!qkv_mode) {
#pragma unroll
        for (int mt = 0; mt < 2; ++mt) {
            const int row0 = bm + wm * 32 + mt * 16 + er;
#pragma unroll
            for (int nt = 0; nt < 8; ++nt) {
                const int col = bn + wn * 64 + nt * 8 + ec;
                float2 v0 = {acc[mt][nt][0], acc[mt][nt][1]};
                float2 v1 = {acc[mt][nt][2], acc[mt][nt][3]};
                *(float2*)(C + (size_t)row0 * N + col)       = v0;
                *(float2*)(C + (size_t)(row0 + 8) * N + col) = v1;
            }
        }
        return;
    }

    // ---- fused QKV epilogue: rope + fp16 conversion ----
    const int gc0 = bn + wn * 64;

    if (gc0 < HID) {
#pragma unroll
        for (int mt = 0; mt < 2; ++mt) {
            const int r0 = bm + wm * 32 + mt * 16 + er;
            const int r1 = r0 + 8;
            const int p0 = r0 & (S_LEN - 1), p1 = r1 & (S_LEN - 1);
#pragma unroll
            for (int nt = 0; nt < 4; ++nt) {
                const int d = nt * 8 + ec;
                float cv00 = rc[p0 * 32 + d],     sv00 = rs[p0 * 32 + d];
                float cv01 = rc[p0 * 32 + d + 1], sv01 = rs[p0 * 32 + d + 1];
                float cv10 = rc[p1 * 32 + d],     sv10 = rs[p1 * 32 + d];
                float cv11 = rc[p1 * 32 + d + 1], sv11 = rs[p1 * 32 + d + 1];
                float x00 = acc[mt][nt][0],     x01 = acc[mt][nt][1];
                float x10 = acc[mt][nt][2],     x11 = acc[mt][nt][3];
                float z00 = acc[mt][nt + 4][0], z01 = acc[mt][nt + 4][1];
                float z10 = acc[mt][nt + 4][2], z11 = acc[mt][nt + 4][3];
                uint32_t hi, lo;
                size_t oA = (size_t)r0 * HID + gc0 + d;
                size_t oB = oA + 32;
                pack_hilo(x00 * cv00 - z00 * sv00, x01 * cv01 - z01 * sv01, hi, lo);
                *(uint32_t*)(qh + oA) = hi; *(uint32_t*)(ql + oA) = lo;
                pack_hilo(z00 * cv00 + x00 * sv00, z01 * cv01 + x01 * sv01, hi, lo);
                *(uint32_t*)(qh + oB) = hi; *(uint32_t*)(ql + oB) = lo;
                size_t oC = (size_t)r1 * HID + gc0 + d;
                size_t oD = oC + 32;
                pack_hilo(x10 * cv10 - z10 * sv10, x11 * cv11 - z11 * sv11, hi, lo);
                *(uint32_t*)(qh + oC) = hi; *(uint32_t*)(ql + oC) = lo;
                pack_hilo(z10 * cv10 + x10 * sv10, z11 * cv11 + x11 * sv11, hi, lo);
                *(uint32_t*)(qh + oD) = hi; *(uint32_t*)(ql + oD) = lo;
            }
        }
    } else if (gc0 < HID + KVDIM) {
        const int cb = gc0 - HID;
#pragma unroll
        for (int mt = 0; mt < 2; ++mt) {
            const int r0 = bm + wm * 32 + mt * 16 + er;
            const int r1 = r0 + 8;
            const int p0 = r0 & (S_LEN - 1), p1 = r1 & (S_LEN - 1);
#pragma unroll
            for (int nt = 0; nt < 4; ++nt) {
                const int d = nt * 8 + ec;
                float cv00 = rc[p0 * 32 + d],     sv00 = rs[p0 * 32 + d];
                float cv01 = rc[p0 * 32 + d + 1], sv01 = rs[p0 * 32 + d + 1];
                float cv10 = rc[p1 * 32 + d],     sv10 = rs[p1 * 32 + d];
                float cv11 = rc[p1 * 32 + d + 1], sv11 = rs[p1 * 32 + d + 1];
                float x00 = acc[mt][nt][0],     x01 = acc[mt][nt][1];
                float x10 = acc[mt][nt][2],     x11 = acc[mt][nt][3];
                float z00 = acc[mt][nt + 4][0], z01 = acc[mt][nt + 4][1];
                float z10 = acc[mt][nt + 4][2], z11 = acc[mt][nt + 4][3];
                __half2 v;
                v = __floats2half2_rn(x00 * cv00 - z00 * sv00, x01 * cv01 - z01 * sv01);
                *(__half2*)(k16 + (size_t)r0 * KVDIM + cb + d) = v;
                v = __floats2half2_rn(z00 * cv00 + x00 * sv00, z01 * cv01 + x01 * sv01);
                *(__half2*)(k16 + (size_t)r0 * KVDIM + cb + d + 32) = v;
                v = __floats2half2_rn(x10 * cv10 - z10 * sv10, x11 * cv11 - z11 * sv11);
                *(__half2*)(k16 + (size_t)r1 * KVDIM + cb + d) = v;
                v = __floats2half2_rn(z10 * cv10 + x10 * sv10, z11 * cv11 + x11 * sv11);
                *(__half2*)(k16 + (size_t)r1 * KVDIM + cb + d + 32) = v;
            }
        }
    } else {
        const int cb = gc0 - HID - KVDIM;
#pragma unroll
        for (int mt = 0; mt < 2; ++mt) {
            const int r0 = bm + wm * 32 + mt * 16 + er;
            const int r1 = r0 + 8;
#pragma unroll
            for (int nt = 0; nt < 8; ++nt) {
                const int d = nt * 8 + ec;
                __half2 v;
                v = __floats2half2_rn(acc[mt][nt][0], acc[mt][nt][1]);
                *(__half2*)(v16 + (size_t)r0 * KVDIM + cb + d) = v;
                v = __floats2half2_rn(acc[mt][nt][2], acc[mt][nt][3]);
                *(__half2*)(v16 + (size_t)r1 * KVDIM + cb + d) = v;
            }
        }
    }
}

// ============================================================================
// Tensor-core flash attention (fp16 2-term, fp32 accum, causal).
// Same compute as the proven 850us version; epilogue writes single fp16.
// ============================================================================
#define AT_ROWB 144
#define AT_TILE (64 * AT_ROWB)
#define AT_QTILE (128 * AT_ROWB)
#define ATTN_SMEM (2 * AT_QTILE + 4 * AT_TILE)   // 73728 B

__global__ __launch_bounds__(256) void attn_mma(
    const __half* __restrict__ qh, const __half* __restrict__ ql,
    const __half* __restrict__ k16, const __half* __restrict__ v16,
    __half* __restrict__ oa)
{
    extern __shared__ char smem[];
    const uint32_t sbase = smem_to_u32(smem);

    const int qt  = (int)(gridDim.x - 1 - blockIdx.x);   // heavy-first
    const int h   = blockIdx.y;
    const int b   = blockIdx.z;
    const int kvh = h >> 2;
    const int q0  = qt << 7;
    const int tid = threadIdx.x;
    const int warp = tid >> 5;
    const int lane = tid & 31;

    const uint32_t sQh = sbase;
    const uint32_t sQl = sbase + AT_QTILE;
    auto kvtile = [&](int buf, int t) -> uint32_t {
        return sbase + 2 * AT_QTILE + (buf * 2 + t) * AT_TILE;
    };

    {
        const int lrow = tid >> 1;
        const int lsg  = (tid & 1) * 4;
        const size_t grow = (size_t)(b * S_LEN + q0 + lrow) * HID + h * HDIM;
#pragma unroll
        for (int i = 0; i < 4; ++i) {
            int seg = lsg + i;
            uint32_t so = (uint32_t)(lrow * AT_ROWB + seg * 16);
            CP_ASYNC16(sQh + so, qh + grow + seg * 8);
            CP_ASYNC16(sQl + so, ql + grow + seg * 8);
        }
        CP_COMMIT();
    }

    const int krow = tid >> 2;
    const int ksg  = (tid & 3) * 2;
    auto issue_kv = [&](int kt, int buf) {
        const size_t grow = (size_t)(b * S_LEN + kt * 64 + krow) * KVDIM + kvh * HDIM;
        const uint32_t t0 = kvtile(buf, 0), t1 = kvtile(buf, 1);
#pragma unroll
        for (int i = 0; i < 2; ++i) {
            int seg = ksg + i;
            uint32_t so = (uint32_t)(krow * AT_ROWB + seg * 16);
            CP_ASYNC16(t0 + so, k16 + grow + seg * 8);
            CP_ASYNC16(t1 + so, v16 + grow + seg * 8);
        }
        CP_COMMIT();
    };

    issue_kv(0, 0);

    const uint32_t a_row  = (uint32_t)(warp * 16 + (lane & 15));
    const uint32_t a_colb = (uint32_t)((lane >> 4) * 16);
    const uint32_t kb_row = (uint32_t)(lane & 7);
    const uint32_t kb_sel = (uint32_t)(((lane >> 3) & 1) * 16);
    const uint32_t v_row  = (uint32_t)(lane & 15);

    const int er = lane >> 2;
    const int ec = (lane & 3) * 2;
    const int qg0 = q0 + warp * 16 + er;
    const int qg1 = qg0 + 8;

    uint32_t qhf[4][4], qlf[4][4];

    float o[8][4];
#pragma unroll
    for (int i = 0; i < 8; ++i)
#pragma unroll
        for (int c = 0; c < 4; ++c) o[i][c] = 0.f;
    float m0 = -INFINITY, m1 = -INFINITY, l0 = 0.f, l1 = 0.f;

    const int NT = 2 * qt + 2;

    for (int kt = 0; kt < NT; ++kt) {
        const int buf = kt & 1;
        if (kt + 1 < NT) { issue_kv(kt + 1, buf ^ 1); CP_WAIT(1); }
        else             { CP_WAIT(0); }
        __syncthreads();

        if (kt == 0) {
#pragma unroll
            for (int ks = 0; ks < 4; ++ks) {
                uint32_t off = a_row * AT_ROWB + a_colb + ks * 32;
                ldsm_x4(qhf[ks], sQh + off);
                ldsm_x4(qlf[ks], sQl + off);
            }
        }

        // ---- S = Q K^T (2-term), ks-outer with hi/lo sweeps ----
        float s[8][4];
#pragma unroll
        for (int nt = 0; nt < 8; ++nt)
#pragma unroll
            for (int c = 0; c < 4; ++c) s[nt][c] = 0.f;

        const uint32_t sK = kvtile(buf, 0);
#pragma unroll
        for (int ks = 0; ks < 4; ++ks) {
            uint32_t kf[8][2];
#pragma unroll
            for (int nt = 0; nt < 8; ++nt)
                ldsm_x2(kf[nt], sK + (nt * 8 + kb_row) * AT_ROWB + kb_sel + ks * 32);
#pragma unroll
            for (int nt = 0; nt < 8; ++nt)
                mma16816(s[nt], qhf[ks], kf[nt]);
#pragma unroll
            for (int nt = 0; nt < 8; ++nt)
                mma16816(s[nt], qlf[ks], kf[nt]);
        }

        const int k0 = kt << 6;
#pragma unroll
        for (int nt = 0; nt < 8; ++nt)
#pragma unroll
            for (int c = 0; c < 4; ++c) s[nt][c] *= 0.125f;

        if (kt >= 2 * qt) {
#pragma unroll
            for (int nt = 0; nt < 8; ++nt) {
                int kg = k0 + nt * 8 + ec;
                if (kg     > qg0) s[nt][0] = -INFINITY;
                if (kg + 1 > qg0) s[nt][1] = -INFINITY;
                if (kg     > qg1) s[nt][2] = -INFINITY;
                if (kg + 1 > qg1) s[nt][3] = -INFINITY;
            }
        }

        // ---- online softmax ----
        float mx0 = -INFINITY, mx1 = -INFINITY;
#pragma unroll
        for (int nt = 0; nt < 8; ++nt) {
            mx0 = fmaxf(mx0, fmaxf(s[nt][0], s[nt][1]));
            mx1 = fmaxf(mx1, fmaxf(s[nt][2], s[nt][3]));
        }
        mx0 = fmaxf(mx0, __shfl_xor_sync(0xffffffffu, mx0, 1));
        mx0 = fmaxf(mx0, __shfl_xor_sync(0xffffffffu, mx0, 2));
        mx1 = fmaxf(mx1, __shfl_xor_sync(0xffffffffu, mx1, 1));
        mx1 = fmaxf(mx1, __shfl_xor_sync(0xffffffffu, mx1, 2));

        float mn0 = fmaxf(m0, mx0), mn1 = fmaxf(m1, mx1);
        float cr0 = __expf(m0 - mn0), cr1 = __expf(m1 - mn1);

        float ls0 = 0.f, ls1 = 0.f;
#pragma unroll
        for (int nt = 0; nt < 8; ++nt) {
            s[nt][0] = __expf(s[nt][0] - mn0);
            s[nt][1] = __expf(s[nt][1] - mn0);
            s[nt][2] = __expf(s[nt][2] - mn1);
            s[nt][3] = __expf(s[nt][3] - mn1);
            ls0 += s[nt][0] + s[nt][1];
            ls1 += s[nt][2] + s[nt][3];
        }
        ls0 += __shfl_xor_sync(0xffffffffu, ls0, 1);
        ls0 += __shfl_xor_sync(0xffffffffu, ls0, 2);
        ls1 += __shfl_xor_sync(0xffffffffu, ls1, 1);
        ls1 += __shfl_xor_sync(0xffffffffu, ls1, 2);
        l0 = l0 * cr0 + ls0;
        l1 = l1 * cr1 + ls1;
        m0 = mn0; m1 = mn1;

#pragma unroll
        for (int nt = 0; nt < 8; ++nt) {
            o[nt][0] *= cr0; o[nt][1] *= cr0;
            o[nt][2] *= cr1; o[nt][3] *= cr1;
        }

        // ---- pack P -> fp16 hi/lo fragments ----
        uint32_t ph[4][4], pl[4][4];
#pragma unroll
        for (int ks = 0; ks < 4; ++ks) {
            pack_hilo(s[2 * ks][0],     s[2 * ks][1],     ph[ks][0], pl[ks][0]);
            pack_hilo(s[2 * ks][2],     s[2 * ks][3],     ph[ks][1], pl[ks][1]);
            pack_hilo(s[2 * ks + 1][0], s[2 * ks + 1][1], ph[ks][2], pl[ks][2]);
            pack_hilo(s[2 * ks + 1][2], s[2 * ks + 1][3], ph[ks][3], pl[ks][3]);
        }

        // ---- O += P V (2-term), ks-outer with hi/lo sweeps ----
        const uint32_t sV = kvtile(buf, 1);
#pragma unroll
        for (int ks = 0; ks < 4; ++ks) {
            uint32_t vf[8][2];
#pragma unroll
            for (int nt = 0; nt < 8; ++nt)
                ldsm_x2_trans(vf[nt], sV + (ks * 16 + v_row) * AT_ROWB + nt * 16);
#pragma unroll
            for (int nt = 0; nt < 8; ++nt)
                mma16816(o[nt], ph[ks], vf[nt]);
#pragma unroll
            for (int nt = 0; nt < 8; ++nt)
                mma16816(o[nt], pl[ks], vf[nt]);
        }
        __syncthreads();
    }

    // ---- epilogue: single fp16 output ----
    const float il0 = 1.f / l0, il1 = 1.f / l1;
    const size_t row0 = (size_t)(b * S_LEN + qg0);
    const size_t row1 = (size_t)(b * S_LEN + qg1);
#pragma unroll
    for (int nt = 0; nt < 8; ++nt) {
        const int col = h * HDIM + nt * 8 + ec;
        __half2 v;
        v = __floats2half2_rn(o[nt][0] * il0, o[nt][1] * il0);
        *(__half2*)(oa + row0 * HID + col) = v;
        v = __floats2half2_rn(o[nt][2] * il1, o[nt][3] * il1);
        *(__half2*)(oa + row1 * HID + col) = v;
    }
}

// ============================================================================
// kernel_launch
// ============================================================================
extern "C" void kernel_launch(void* const* d_in, const int* in_sizes, int n_in,
                              void* d_out, int out_size)
{
    (void)in_sizes; (void)n_in; (void)out_size;
    const float* x  = (const float*)d_in[0];
    const float* Wq = (const float*)d_in[1];
    const float* Wk = (const float*)d_in[2];
    const float* Wv = (const float*)d_in[3];
    const float* Wo = (const float*)d_in[4];
    float* out = (float*)d_out;

    float *rc, *rs;
    cudaGetSymbolAddress((void**)&rc, g_rc);
    cudaGetSymbolAddress((void**)&rs, g_rs);

    __half *xh, *xl, *w3, *wo, *a16, *qhb, *qlb, *k16, *v16;
    cudaGetSymbolAddress((void**)&xh,  g_xh);
    cudaGetSymbolAddress((void**)&xl,  g_xl);
    cudaGetSymbolAddress((void**)&w3,  g_w3);
    cudaGetSymbolAddress((void**)&wo,  g_wo);
    cudaGetSymbolAddress((void**)&a16, g_a16);
    cudaGetSymbolAddress((void**)&qhb, g_qh);
    cudaGetSymbolAddress((void**)&qlb, g_ql);
    cudaGetSymbolAddress((void**)&k16, g_k16);
    cudaGetSymbolAddress((void**)&v16, g_v16);

    cudaFuncSetAttribute(gemm_mma, cudaFuncAttributeMaxDynamicSharedMemorySize, GEMM_SMEM);
    cudaFuncSetAttribute(attn_mma, cudaFuncAttributeMaxDynamicSharedMemorySize, ATTN_SMEM);

    const int M = MROWS;
    const int nx = M * HID;
    const int nconv = (QKVN * HID + HID * HID) / 4;

    // rope tables
    rope_table<<<(S_LEN * 32 + 255) / 256, 256>>>(rc, rs);

    // x split
    split_fp16_v4<<<(nx / 4 + 255) / 256, 256>>>((const float4*)x, (uint2*)xh, (uint2*)xl, nx / 4);

    // all weight converts in one launch
    conv_weights_v4<<<(nconv + 255) / 256, 256>>>(
        (const float4*)Wq, (const float4*)Wk, (const float4*)Wv, (const float4*)Wo,
        (uint2*)w3, (uint2*)wo);

    // fused QKV projection with rope+fp16 epilogue (2-term)
    gemm_mma<<<dim3(QKVN / BN, M / BM), 256, GEMM_SMEM>>>(
        xh, xl, w3, nullptr, M, QKVN, HID,
        1, 1, rc, rs, qhb, qlb, k16, v16);

    // causal flash attention (heavy-first), single-fp16 output
    attn_mma<<<dim3(S_LEN / 128, NHEADS, BATCH), 256, ATTN_SMEM>>>(
        qhb, qlb, k16, v16, a16);

    // output projection (1-term: A = attention out, single fp16)
    gemm_mma<<<dim3(HID / BN, M / BM), 256, GEMM_SMEM>>>(
        a16, nullptr, wo, out, M, HID, HID,
        0, 0, nullptr, nullptr, nullptr, nullptr, nullptr, nullptr);
}

// round 16
// speedup vs baseline: 2.0289x; 1.3562x over previous
#include <cuda_runtime.h>
#include <cuda_fp16.h>
#include <math.h>
#include <stdint.h>

#define S_LEN   2048
#define BATCH   2
#define HID     2048
#define NHEADS  32
#define KVHEADS 8
#define HDIM    64
#define MROWS   (BATCH * S_LEN)     // 4096
#define KVDIM   (KVHEADS * HDIM)    // 512
#define QKVN    (HID + 2 * KVDIM)   // 3072

// ---------------- scratch (static device globals; no allocations) ----------
__device__ __half g_x16[(size_t)MROWS * HID];      // x (single fp16)
__device__ __half g_w3 [(size_t)QKVN * HID];
__device__ __half g_wo [(size_t)HID * HID];
__device__ __half g_a16[(size_t)MROWS * HID];      // attention out (single fp16)

__device__ __half g_qh [(size_t)MROWS * HID];      // rotated Q hi
__device__ __half g_ql [(size_t)MROWS * HID];      // rotated Q lo
__device__ __half g_k16[(size_t)MROWS * KVDIM];
__device__ __half g_v16[(size_t)MROWS * KVDIM];

__device__ float g_rc[S_LEN * 32];
__device__ float g_rs[S_LEN * 32];

// ============================================================================
// PTX helpers (plain sm_103-safe)
// ============================================================================
__device__ __forceinline__ uint32_t smem_to_u32(const void* p) {
    uint32_t a;
    asm("{ .reg .u64 t; cvta.to.shared.u64 t, %1; cvt.u32.u64 %0, t; }"
        : "=r"(a) : "l"(p));
    return a;
}

#define CP_ASYNC16(smem, gmem) \
    asm volatile("cp.async.cg.shared.global [%0], [%1], 16;" \
                 :: "r"(smem), "l"(gmem) : "memory")
#define CP_COMMIT() asm volatile("cp.async.commit_group;" ::: "memory")
#define CP_WAIT(n)  asm volatile("cp.async.wait_group %0;" :: "n"(n) : "memory")

__device__ __forceinline__ void ldsm_x4(uint32_t* r, uint32_t addr) {
    asm volatile("ldmatrix.sync.aligned.m8n8.x4.shared.b16 {%0,%1,%2,%3}, [%4];"
        : "=r"(r[0]), "=r"(r[1]), "=r"(r[2]), "=r"(r[3]) : "r"(addr));
}
__device__ __forceinline__ void ldsm_x2(uint32_t* r, uint32_t addr) {
    asm volatile("ldmatrix.sync.aligned.m8n8.x2.shared.b16 {%0,%1}, [%2];"
        : "=r"(r[0]), "=r"(r[1]) : "r"(addr));
}
__device__ __forceinline__ void ldsm_x2_trans(uint32_t* r, uint32_t addr) {
    asm volatile("ldmatrix.sync.aligned.m8n8.x2.trans.shared.b16 {%0,%1}, [%2];"
        : "=r"(r[0]), "=r"(r[1]) : "r"(addr));
}

__device__ __forceinline__ void mma16816(float* d, const uint32_t* a, const uint32_t* b) {
    asm volatile(
        "mma.sync.aligned.m16n8k16.row.col.f32.f16.f16.f32 "
        "{%0,%1,%2,%3}, {%4,%5,%6,%7}, {%8,%9}, {%0,%1,%2,%3};"
        : "+f"(d[0]), "+f"(d[1]), "+f"(d[2]), "+f"(d[3])
        : "r"(a[0]), "r"(a[1]), "r"(a[2]), "r"(a[3]), "r"(b[0]), "r"(b[1]));
}

__device__ __forceinline__ void pack_hilo(float a, float b, uint32_t& hi, uint32_t& lo) {
    __half ha = __float2half_rn(a);
    __half hb = __float2half_rn(b);
    __half2 H; H.x = ha; H.y = hb;
    hi = *reinterpret_cast<uint32_t*>(&H);
    __half2 L;
    L.x = __float2half_rn(a - __half2float(ha));
    L.y = __float2half_rn(b - __half2float(hb));
    lo = *reinterpret_cast<uint32_t*>(&L);
}

// ============================================================================
// vectorized fp32 -> fp16 convert
// ============================================================================
__global__ void conv_fp16_v4(const float4* __restrict__ in, uint2* __restrict__ out, int n4)
{
    int i = blockIdx.x * blockDim.x + threadIdx.x;
    if (i >= n4) return;
    float4 v = in[i];
    __half2 h0 = __floats2half2_rn(v.x, v.y);
    __half2 h1 = __floats2half2_rn(v.z, v.w);
    uint2 H = {*reinterpret_cast<uint32_t*>(&h0), *reinterpret_cast<uint32_t*>(&h1)};
    out[i] = H;
}

// fused Wq|Wk|Wv -> w3  and  Wo -> wo  (one launch)
__global__ void conv_weights_v4(const float4* __restrict__ wq, const float4* __restrict__ wk,
                                const float4* __restrict__ wv, const float4* __restrict__ woin,
                                uint2* __restrict__ w3, uint2* __restrict__ wo)
{
    const int nq = HID * HID / 4;
    const int nk = KVDIM * HID / 4;
    const int n3 = nq + 2 * nk;
    const int tot = n3 + nq;
    int i = blockIdx.x * blockDim.x + threadIdx.x;
    if (i >= tot) return;
    float4 v;
    uint2* dst;
    int oi;
    if (i < nq)            { v = wq[i];            dst = w3; oi = i; }
    else if (i < nq + nk)  { v = wk[i - nq];       dst = w3; oi = i; }
    else if (i < n3)       { v = wv[i - nq - nk];  dst = w3; oi = i; }
    else                   { v = woin[i - n3];     dst = wo; oi = i - n3; }
    __half2 h0 = __floats2half2_rn(v.x, v.y);
    __half2 h1 = __floats2half2_rn(v.z, v.w);
    uint2 H = {*reinterpret_cast<uint32_t*>(&h0), *reinterpret_cast<uint32_t*>(&h1)};
    dst[oi] = H;
}

// ============================================================================
// RoPE table
// ============================================================================
__global__ void rope_table(float* __restrict__ ct, float* __restrict__ st)
{
    int t = blockIdx.x * blockDim.x + threadIdx.x;
    if (t >= S_LEN * 32) return;
    int pos  = t >> 5;
    int pair = t & 31;
    float inv = (float)exp(-(double)pair * (9.210340371976184 / 32.0));
    float a = (float)pos * inv;
    float s, c;
    sincosf(a, &s, &c);
    ct[t] = c;
    st[t] = s;
}

// ============================================================================
// fp16 1-term GEMM via mma.sync, 2-stage cp.async (2 CTAs/SM),
// 4x2 warp grid (warp tile 32x64), 256 threads.
// C[M,N] = A[M,K] @ B[N,K]^T, single-fp16 operands, fp32 accum.
// qkv_mode: fused rope + fp16 hi/lo(Q) / single(K,V) epilogue.
// ============================================================================
#define BM 128
#define BN 128
#define BK 32
#define ROWB   80
#define ASZ    (128 * ROWB)
#define STAGE  (2 * ASZ)                 // A, B tile slots
#define GEMM_SMEM (2 * STAGE)            // 40960 B

__global__ __launch_bounds__(256) void gemm_mma(
    const __half* __restrict__ A, const __half* __restrict__ B,
    float* __restrict__ C, int M, int N, int K,
    int qkv_mode,
    const float* __restrict__ rc, const float* __restrict__ rs,
    __half* __restrict__ qh, __half* __restrict__ ql,
    __half* __restrict__ k16, __half* __restrict__ v16)
{
    extern __shared__ char smem[];
    const uint32_t sbase = smem_to_u32(smem);

    const int tid  = threadIdx.x;
    const int wid  = tid >> 5;
    const int lane = tid & 31;
    const int wm   = wid >> 1;        // 0..3 (row band)
    const int wn   = wid & 1;         // 0..1 (col band, 64 cols = one head)
    const int bm   = blockIdx.y * BM;
    const int bn   = blockIdx.x * BN;

    const __half* gA = A + (size_t)bm * K;
    const __half* gB = B + (size_t)bn * K;

    const int NC = K / BK;

    const int lr  = tid >> 2;
    const int lsg = tid & 3;
    auto issue = [&](int kc, int buf) {
        const uint32_t sb = sbase + buf * STAGE;
        const size_t kofs = (size_t)kc * BK + lsg * 8;
#pragma unroll
        for (int t = 0; t < 2; ++t) {
            int r = lr + t * 64;
            uint32_t so = (uint32_t)(r * ROWB + lsg * 16);
            size_t g = (size_t)r * K + kofs;
            CP_ASYNC16(sb + so,       gA + g);
            CP_ASYNC16(sb + ASZ + so, gB + g);
        }
        CP_COMMIT();
    };

    float acc[2][8][4];
#pragma unroll
    for (int i = 0; i < 2; ++i)
#pragma unroll
        for (int j = 0; j < 8; ++j)
#pragma unroll
            for (int c = 0; c < 4; ++c) acc[i][j][c] = 0.f;

    const uint32_t a_row  = (uint32_t)(wm * 32 + (lane & 15));
    const uint32_t a_colb = (uint32_t)((lane >> 4) * 16);
    const uint32_t bp_row = (uint32_t)(wn * 64 + ((lane >> 4) << 3) + (lane & 7));
    const uint32_t bp_sel = (uint32_t)(((lane >> 3) & 1) * 16);

    issue(0, 0);
    issue(1, 1);

    for (int kt = 0; kt < NC; ++kt) {
        const int buf = kt & 1;
        if (kt + 2 <= NC) { CP_WAIT(1); }
        else              { CP_WAIT(0); }
        __syncthreads();

        const uint32_t sA = sbase + buf * STAGE;
        const uint32_t sB = sA + ASZ;

#pragma unroll
        for (int ks = 0; ks < 2; ++ks) {
            const uint32_t kofs = ks * 32;

            uint32_t ar[2][4], bb[4][4];
#pragma unroll
            for (int mt = 0; mt < 2; ++mt) {
                uint32_t off = (a_row + mt * 16) * ROWB + a_colb + kofs;
                ldsm_x4(ar[mt], sA + off);
            }
#pragma unroll
            for (int ntp = 0; ntp < 4; ++ntp) {
                uint32_t off = (bp_row + ntp * 16) * ROWB + bp_sel + kofs;
                ldsm_x4(bb[ntp], sB + off);
            }
#pragma unroll
            for (int mt = 0; mt < 2; ++mt)
#pragma unroll
                for (int nt = 0; nt < 8; ++nt) {
                    const uint32_t* bf = &bb[nt >> 1][(nt & 1) * 2];
                    mma16816(acc[mt][nt], ar[mt], bf);
                }
        }
        __syncthreads();

        if (kt + 2 < NC) issue(kt + 2, buf);
    }

    const int er = lane >> 2;
    const int ec = (lane & 3) * 2;

    if (!qkv_mode) {
#pragma unroll
        for (int mt = 0; mt < 2; ++mt) {
            const int row0 = bm + wm * 32 + mt * 16 + er;
#pragma unroll
            for (int nt = 0; nt < 8; ++nt) {
                const int col = bn + wn * 64 + nt * 8 + ec;
                float2 v0 = {acc[mt][nt][0], acc[mt][nt][1]};
                float2 v1 = {acc[mt][nt][2], acc[mt][nt][3]};
                *(float2*)(C + (size_t)row0 * N + col)       = v0;
                *(float2*)(C + (size_t)(row0 + 8) * N + col) = v1;
            }
        }
        return;
    }

    // ---- fused QKV epilogue: rope + fp16 conversion ----
    const int gc0 = bn + wn * 64;

    if (gc0 < HID) {
#pragma unroll
        for (int mt = 0; mt < 2; ++mt) {
            const int r0 = bm + wm * 32 + mt * 16 + er;
            const int r1 = r0 + 8;
            const int p0 = r0 & (S_LEN - 1), p1 = r1 & (S_LEN - 1);
#pragma unroll
            for (int nt = 0; nt < 4; ++nt) {
                const int d = nt * 8 + ec;
                float cv00 = rc[p0 * 32 + d],     sv00 = rs[p0 * 32 + d];
                float cv01 = rc[p0 * 32 + d + 1], sv01 = rs[p0 * 32 + d + 1];
                float cv10 = rc[p1 * 32 + d],     sv10 = rs[p1 * 32 + d];
                float cv11 = rc[p1 * 32 + d + 1], sv11 = rs[p1 * 32 + d + 1];
                float x00 = acc[mt][nt][0],     x01 = acc[mt][nt][1];
                float x10 = acc[mt][nt][2],     x11 = acc[mt][nt][3];
                float z00 = acc[mt][nt + 4][0], z01 = acc[mt][nt + 4][1];
                float z10 = acc[mt][nt + 4][2], z11 = acc[mt][nt + 4][3];
                uint32_t hi, lo;
                size_t oA = (size_t)r0 * HID + gc0 + d;
                size_t oB = oA + 32;
                pack_hilo(x00 * cv00 - z00 * sv00, x01 * cv01 - z01 * sv01, hi, lo);
                *(uint32_t*)(qh + oA) = hi; *(uint32_t*)(ql + oA) = lo;
                pack_hilo(z00 * cv00 + x00 * sv00, z01 * cv01 + x01 * sv01, hi, lo);
                *(uint32_t*)(qh + oB) = hi; *(uint32_t*)(ql + oB) = lo;
                size_t oC = (size_t)r1 * HID + gc0 + d;
                size_t oD = oC + 32;
                pack_hilo(x10 * cv10 - z10 * sv10, x11 * cv11 - z11 * sv11, hi, lo);
                *(uint32_t*)(qh + oC) = hi; *(uint32_t*)(ql + oC) = lo;
                pack_hilo(z10 * cv10 + x10 * sv10, z11 * cv11 + x11 * sv11, hi, lo);
                *(uint32_t*)(qh + oD) = hi; *(uint32_t*)(ql + oD) = lo;
            }
        }
    } else if (gc0 < HID + KVDIM) {
        const int cb = gc0 - HID;
#pragma unroll
        for (int mt = 0; mt < 2; ++mt) {
            const int r0 = bm + wm * 32 + mt * 16 + er;
            const int r1 = r0 + 8;
            const int p0 = r0 & (S_LEN - 1), p1 = r1 & (S_LEN - 1);
#pragma unroll
            for (int nt = 0; nt < 4; ++nt) {
                const int d = nt * 8 + ec;
                float cv00 = rc[p0 * 32 + d],     sv00 = rs[p0 * 32 + d];
                float cv01 = rc[p0 * 32 + d + 1], sv01 = rs[p0 * 32 + d + 1];
                float cv10 = rc[p1 * 32 + d],     sv10 = rs[p1 * 32 + d];
                float cv11 = rc[p1 * 32 + d + 1], sv11 = rs[p1 * 32 + d + 1];
                float x00 = acc[mt][nt][0],     x01 = acc[mt][nt][1];
                float x10 = acc[mt][nt][2],     x11 = acc[mt][nt][3];
                float z00 = acc[mt][nt + 4][0], z01 = acc[mt][nt + 4][1];
                float z10 = acc[mt][nt + 4][2], z11 = acc[mt][nt + 4][3];
                __half2 v;
                v = __floats2half2_rn(x00 * cv00 - z00 * sv00, x01 * cv01 - z01 * sv01);
                *(__half2*)(k16 + (size_t)r0 * KVDIM + cb + d) = v;
                v = __floats2half2_rn(z00 * cv00 + x00 * sv00, z01 * cv01 + x01 * sv01);
                *(__half2*)(k16 + (size_t)r0 * KVDIM + cb + d + 32) = v;
                v = __floats2half2_rn(x10 * cv10 - z10 * sv10, x11 * cv11 - z11 * sv11);
                *(__half2*)(k16 + (size_t)r1 * KVDIM + cb + d) = v;
                v = __floats2half2_rn(z10 * cv10 + x10 * sv10, z11 * cv11 + x11 * sv11);
                *(__half2*)(k16 + (size_t)r1 * KVDIM + cb + d + 32) = v;
            }
        }
    } else {
        const int cb = gc0 - HID - KVDIM;
#pragma unroll
        for (int mt = 0; mt < 2; ++mt) {
            const int r0 = bm + wm * 32 + mt * 16 + er;
            const int r1 = r0 + 8;
#pragma unroll
            for (int nt = 0; nt < 8; ++nt) {
                const int d = nt * 8 + ec;
                __half2 v;
                v = __floats2half2_rn(acc[mt][nt][0], acc[mt][nt][1]);
                *(__half2*)(v16 + (size_t)r0 * KVDIM + cb + d) = v;
                v = __floats2half2_rn(acc[mt][nt][2], acc[mt][nt][3]);
                *(__half2*)(v16 + (size_t)r1 * KVDIM + cb + d) = v;
            }
        }
    }
}

// ============================================================================
// Tensor-core flash attention (causal): QK^T 2-term (Q hi/lo, K single),
// P·V 1-term (P single fp16). Single-fp16 output.
// ============================================================================
#define AT_ROWB 144
#define AT_TILE (64 * AT_ROWB)
#define AT_QTILE (128 * AT_ROWB)
#define ATTN_SMEM (2 * AT_QTILE + 4 * AT_TILE)   // 73728 B

__global__ __launch_bounds__(256) void attn_mma(
    const __half* __restrict__ qh, const __half* __restrict__ ql,
    const __half* __restrict__ k16, const __half* __restrict__ v16,
    __half* __restrict__ oa)
{
    extern __shared__ char smem[];
    const uint32_t sbase = smem_to_u32(smem);

    const int qt  = (int)(gridDim.x - 1 - blockIdx.x);   // heavy-first
    const int h   = blockIdx.y;
    const int b   = blockIdx.z;
    const int kvh = h >> 2;
    const int q0  = qt << 7;
    const int tid = threadIdx.x;
    const int warp = tid >> 5;
    const int lane = tid & 31;

    const uint32_t sQh = sbase;
    const uint32_t sQl = sbase + AT_QTILE;
    auto kvtile = [&](int buf, int t) -> uint32_t {
        return sbase + 2 * AT_QTILE + (buf * 2 + t) * AT_TILE;
    };

    {
        const int lrow = tid >> 1;
        const int lsg  = (tid & 1) * 4;
        const size_t grow = (size_t)(b * S_LEN + q0 + lrow) * HID + h * HDIM;
#pragma unroll
        for (int i = 0; i < 4; ++i) {
            int seg = lsg + i;
            uint32_t so = (uint32_t)(lrow * AT_ROWB + seg * 16);
            CP_ASYNC16(sQh + so, qh + grow + seg * 8);
            CP_ASYNC16(sQl + so, ql + grow + seg * 8);
        }
        CP_COMMIT();
    }

    const int krow = tid >> 2;
    const int ksg  = (tid & 3) * 2;
    auto issue_kv = [&](int kt, int buf) {
        const size_t grow = (size_t)(b * S_LEN + kt * 64 + krow) * KVDIM + kvh * HDIM;
        const uint32_t t0 = kvtile(buf, 0), t1 = kvtile(buf, 1);
#pragma unroll
        for (int i = 0; i < 2; ++i) {
            int seg = ksg + i;
            uint32_t so = (uint32_t)(krow * AT_ROWB + seg * 16);
            CP_ASYNC16(t0 + so, k16 + grow + seg * 8);
            CP_ASYNC16(t1 + so, v16 + grow + seg * 8);
        }
        CP_COMMIT();
    };

    issue_kv(0, 0);

    const uint32_t a_row  = (uint32_t)(warp * 16 + (lane & 15));
    const uint32_t a_colb = (uint32_t)((lane >> 4) * 16);
    const uint32_t kb_row = (uint32_t)(lane & 7);
    const uint32_t kb_sel = (uint32_t)(((lane >> 3) & 1) * 16);
    const uint32_t v_row  = (uint32_t)(lane & 15);

    const int er = lane >> 2;
    const int ec = (lane & 3) * 2;
    const int qg0 = q0 + warp * 16 + er;
    const int qg1 = qg0 + 8;

    uint32_t qhf[4][4], qlf[4][4];

    float o[8][4];
#pragma unroll
    for (int i = 0; i < 8; ++i)
#pragma unroll
        for (int c = 0; c < 4; ++c) o[i][c] = 0.f;
    float m0 = -INFINITY, m1 = -INFINITY, l0 = 0.f, l1 = 0.f;

    const int NT = 2 * qt + 2;

    for (int kt = 0; kt < NT; ++kt) {
        const int buf = kt & 1;
        if (kt + 1 < NT) { issue_kv(kt + 1, buf ^ 1); CP_WAIT(1); }
        else             { CP_WAIT(0); }
        __syncthreads();

        if (kt == 0) {
#pragma unroll
            for (int ks = 0; ks < 4; ++ks) {
                uint32_t off = a_row * AT_ROWB + a_colb + ks * 32;
                ldsm_x4(qhf[ks], sQh + off);
                ldsm_x4(qlf[ks], sQl + off);
            }
        }

        // ---- S = Q K^T (2-term: Q hi/lo) ----
        float s[8][4];
#pragma unroll
        for (int nt = 0; nt < 8; ++nt)
#pragma unroll
            for (int c = 0; c < 4; ++c) s[nt][c] = 0.f;

        const uint32_t sK = kvtile(buf, 0);
#pragma unroll
        for (int ks = 0; ks < 4; ++ks) {
            uint32_t kf[8][2];
#pragma unroll
            for (int nt = 0; nt < 8; ++nt)
                ldsm_x2(kf[nt], sK + (nt * 8 + kb_row) * AT_ROWB + kb_sel + ks * 32);
#pragma unroll
            for (int nt = 0; nt < 8; ++nt)
                mma16816(s[nt], qhf[ks], kf[nt]);
#pragma unroll
            for (int nt = 0; nt < 8; ++nt)
                mma16816(s[nt], qlf[ks], kf[nt]);
        }

        const int k0 = kt << 6;
#pragma unroll
        for (int nt = 0; nt < 8; ++nt)
#pragma unroll
            for (int c = 0; c < 4; ++c) s[nt][c] *= 0.125f;

        if (kt >= 2 * qt) {
#pragma unroll
            for (int nt = 0; nt < 8; ++nt) {
                int kg = k0 + nt * 8 + ec;
                if (kg     > qg0) s[nt][0] = -INFINITY;
                if (kg + 1 > qg0) s[nt][1] = -INFINITY;
                if (kg     > qg1) s[nt][2] = -INFINITY;
                if (kg + 1 > qg1) s[nt][3] = -INFINITY;
            }
        }

        // ---- online softmax ----
        float mx0 = -INFINITY, mx1 = -INFINITY;
#pragma unroll
        for (int nt = 0; nt < 8; ++nt) {
            mx0 = fmaxf(mx0, fmaxf(s[nt][0], s[nt][1]));
            mx1 = fmaxf(mx1, fmaxf(s[nt][2], s[nt][3]));
        }
        mx0 = fmaxf(mx0, __shfl_xor_sync(0xffffffffu, mx0, 1));
        mx0 = fmaxf(mx0, __shfl_xor_sync(0xffffffffu, mx0, 2));
        mx1 = fmaxf(mx1, __shfl_xor_sync(0xffffffffu, mx1, 1));
        mx1 = fmaxf(mx1, __shfl_xor_sync(0xffffffffu, mx1, 2));

        float mn0 = fmaxf(m0, mx0), mn1 = fmaxf(m1, mx1);
        float cr0 = __expf(m0 - mn0), cr1 = __expf(m1 - mn1);

        float ls0 = 0.f, ls1 = 0.f;
#pragma unroll
        for (int nt = 0; nt < 8; ++nt) {
            s[nt][0] = __expf(s[nt][0] - mn0);
            s[nt][1] = __expf(s[nt][1] - mn0);
            s[nt][2] = __expf(s[nt][2] - mn1);
            s[nt][3] = __expf(s[nt][3] - mn1);
            ls0 += s[nt][0] + s[nt][1];
            ls1 += s[nt][2] + s[nt][3];
        }
        ls0 += __shfl_xor_sync(0xffffffffu, ls0, 1);
        ls0 += __shfl_xor_sync(0xffffffffu, ls0, 2);
        ls1 += __shfl_xor_sync(0xffffffffu, ls1, 1);
        ls1 += __shfl_xor_sync(0xffffffffu, ls1, 2);
        l0 = l0 * cr0 + ls0;
        l1 = l1 * cr1 + ls1;
        m0 = mn0; m1 = mn1;

#pragma unroll
        for (int nt = 0; nt < 8; ++nt) {
            o[nt][0] *= cr0; o[nt][1] *= cr0;
            o[nt][2] *= cr1; o[nt][3] *= cr1;
        }

        // ---- pack P -> single fp16 fragments ----
        uint32_t ph[4][4];
#pragma unroll
        for (int ks = 0; ks < 4; ++ks) {
            __half2 t;
            t = __floats2half2_rn(s[2 * ks][0],     s[2 * ks][1]);
            ph[ks][0] = *reinterpret_cast<uint32_t*>(&t);
            t = __floats2half2_rn(s[2 * ks][2],     s[2 * ks][3]);
            ph[ks][1] = *reinterpret_cast<uint32_t*>(&t);
            t = __floats2half2_rn(s[2 * ks + 1][0], s[2 * ks + 1][1]);
            ph[ks][2] = *reinterpret_cast<uint32_t*>(&t);
            t = __floats2half2_rn(s[2 * ks + 1][2], s[2 * ks + 1][3]);
            ph[ks][3] = *reinterpret_cast<uint32_t*>(&t);
        }

        // ---- O += P V (1-term) ----
        const uint32_t sV = kvtile(buf, 1);
#pragma unroll
        for (int ks = 0; ks < 4; ++ks) {
            uint32_t vf[8][2];
#pragma unroll
            for (int nt = 0; nt < 8; ++nt)
                ldsm_x2_trans(vf[nt], sV + (ks * 16 + v_row) * AT_ROWB + nt * 16);
#pragma unroll
            for (int nt = 0; nt < 8; ++nt)
                mma16816(o[nt], ph[ks], vf[nt]);
        }
        __syncthreads();
    }

    // ---- epilogue: single fp16 output ----
    const float il0 = 1.f / l0, il1 = 1.f / l1;
    const size_t row0 = (size_t)(b * S_LEN + qg0);
    const size_t row1 = (size_t)(b * S_LEN + qg1);
#pragma unroll
    for (int nt = 0; nt < 8; ++nt) {
        const int col = h * HDIM + nt * 8 + ec;
        __half2 v;
        v = __floats2half2_rn(o[nt][0] * il0, o[nt][1] * il0);
        *(__half2*)(oa + row0 * HID + col) = v;
        v = __floats2half2_rn(o[nt][2] * il1, o[nt][3] * il1);
        *(__half2*)(oa + row1 * HID + col) = v;
    }
}

// ============================================================================
// kernel_launch
// ============================================================================
extern "C" void kernel_launch(void* const* d_in, const int* in_sizes, int n_in,
                              void* d_out, int out_size)
{
    (void)in_sizes; (void)n_in; (void)out_size;
    const float* x  = (const float*)d_in[0];
    const float* Wq = (const float*)d_in[1];
    const float* Wk = (const float*)d_in[2];
    const float* Wv = (const float*)d_in[3];
    const float* Wo = (const float*)d_in[4];
    float* out = (float*)d_out;

    float *rc, *rs;
    cudaGetSymbolAddress((void**)&rc, g_rc);
    cudaGetSymbolAddress((void**)&rs, g_rs);

    __half *x16, *w3, *wo, *a16, *qhb, *qlb, *k16, *v16;
    cudaGetSymbolAddress((void**)&x16, g_x16);
    cudaGetSymbolAddress((void**)&w3,  g_w3);
    cudaGetSymbolAddress((void**)&wo,  g_wo);
    cudaGetSymbolAddress((void**)&a16, g_a16);
    cudaGetSymbolAddress((void**)&qhb, g_qh);
    cudaGetSymbolAddress((void**)&qlb, g_ql);
    cudaGetSymbolAddress((void**)&k16, g_k16);
    cudaGetSymbolAddress((void**)&v16, g_v16);

    cudaFuncSetAttribute(gemm_mma, cudaFuncAttributeMaxDynamicSharedMemorySize, GEMM_SMEM);
    cudaFuncSetAttribute(attn_mma, cudaFuncAttributeMaxDynamicSharedMemorySize, ATTN_SMEM);

    const int M = MROWS;
    const int nx = M * HID;
    const int nconv = (QKVN * HID + HID * HID) / 4;

    // rope tables
    rope_table<<<(S_LEN * 32 + 255) / 256, 256>>>(rc, rs);

    // x convert (single fp16)
    conv_fp16_v4<<<(nx / 4 + 255) / 256, 256>>>((const float4*)x, (uint2*)x16, nx / 4);

    // all weight converts in one launch
    conv_weights_v4<<<(nconv + 255) / 256, 256>>>(
        (const float4*)Wq, (const float4*)Wk, (const float4*)Wv, (const float4*)Wo,
        (uint2*)w3, (uint2*)wo);

    // fused QKV projection (1-term) with rope+fp16 epilogue
    gemm_mma<<<dim3(QKVN / BN, M / BM), 256, GEMM_SMEM>>>(
        x16, w3, nullptr, M, QKVN, HID,
        1, rc, rs, qhb, qlb, k16, v16);

    // causal flash attention (heavy-first)
    attn_mma<<<dim3(S_LEN / 128, NHEADS, BATCH), 256, ATTN_SMEM>>>(
        qhb, qlb, k16, v16, a16);

    // output projection (1-term)
    gemm_mma<<<dim3(HID / BN, M / BM), 256, GEMM_SMEM>>>(
        a16, wo, out, M, HID, HID,
        0, nullptr, nullptr, nullptr, nullptr, nullptr, nullptr);
}

// round 17
// speedup vs baseline: 2.2445x; 1.1062x over previous
#include <cuda_runtime.h>
#include <cuda_fp16.h>
#include <math.h>
#include <stdint.h>

#define S_LEN   2048
#define BATCH   2
#define HID     2048
#define NHEADS  32
#define KVHEADS 8
#define HDIM    64
#define MROWS   (BATCH * S_LEN)     // 4096
#define KVDIM   (KVHEADS * HDIM)    // 512
#define QKVN    (HID + 2 * KVDIM)   // 3072

// ---------------- scratch (static device globals; no allocations) ----------
__device__ __half g_x16[(size_t)MROWS * HID];      // x (single fp16)
__device__ __half g_w3 [(size_t)QKVN * HID];
__device__ __half g_wo [(size_t)HID * HID];
__device__ __half g_a16[(size_t)MROWS * HID];      // attention out (single fp16)

__device__ __half g_q16[(size_t)MROWS * HID];      // rotated Q (single fp16)
__device__ __half g_k16[(size_t)MROWS * KVDIM];
__device__ __half g_v16[(size_t)MROWS * KVDIM];

__device__ float g_rc[S_LEN * 32];
__device__ float g_rs[S_LEN * 32];

// ============================================================================
// PTX helpers (plain sm_103-safe)
// ============================================================================
__device__ __forceinline__ uint32_t smem_to_u32(const void* p) {
    uint32_t a;
    asm("{ .reg .u64 t; cvta.to.shared.u64 t, %1; cvt.u32.u64 %0, t; }"
        : "=r"(a) : "l"(p));
    return a;
}

#define CP_ASYNC16(smem, gmem) \
    asm volatile("cp.async.cg.shared.global [%0], [%1], 16;" \
                 :: "r"(smem), "l"(gmem) : "memory")
#define CP_COMMIT() asm volatile("cp.async.commit_group;" ::: "memory")
#define CP_WAIT(n)  asm volatile("cp.async.wait_group %0;" :: "n"(n) : "memory")

__device__ __forceinline__ void ldsm_x4(uint32_t* r, uint32_t addr) {
    asm volatile("ldmatrix.sync.aligned.m8n8.x4.shared.b16 {%0,%1,%2,%3}, [%4];"
        : "=r"(r[0]), "=r"(r[1]), "=r"(r[2]), "=r"(r[3]) : "r"(addr));
}
__device__ __forceinline__ void ldsm_x2(uint32_t* r, uint32_t addr) {
    asm volatile("ldmatrix.sync.aligned.m8n8.x2.shared.b16 {%0,%1}, [%2];"
        : "=r"(r[0]), "=r"(r[1]) : "r"(addr));
}
__device__ __forceinline__ void ldsm_x2_trans(uint32_t* r, uint32_t addr) {
    asm volatile("ldmatrix.sync.aligned.m8n8.x2.trans.shared.b16 {%0,%1}, [%2];"
        : "=r"(r[0]), "=r"(r[1]) : "r"(addr));
}

__device__ __forceinline__ void mma16816(float* d, const uint32_t* a, const uint32_t* b) {
    asm volatile(
        "mma.sync.aligned.m16n8k16.row.col.f32.f16.f16.f32 "
        "{%0,%1,%2,%3}, {%4,%5,%6,%7}, {%8,%9}, {%0,%1,%2,%3};"
        : "+f"(d[0]), "+f"(d[1]), "+f"(d[2]), "+f"(d[3])
        : "r"(a[0]), "r"(a[1]), "r"(a[2]), "r"(a[3]), "r"(b[0]), "r"(b[1]));
}

// ============================================================================
// vectorized fp32 -> fp16 convert
// ============================================================================
__global__ void conv_fp16_v4(const float4* __restrict__ in, uint2* __restrict__ out, int n4)
{
    int i = blockIdx.x * blockDim.x + threadIdx.x;
    if (i >= n4) return;
    float4 v = in[i];
    __half2 h0 = __floats2half2_rn(v.x, v.y);
    __half2 h1 = __floats2half2_rn(v.z, v.w);
    uint2 H = {*reinterpret_cast<uint32_t*>(&h0), *reinterpret_cast<uint32_t*>(&h1)};
    out[i] = H;
}

// fused Wq|Wk|Wv -> w3  and  Wo -> wo  (one launch)
__global__ void conv_weights_v4(const float4* __restrict__ wq, const float4* __restrict__ wk,
                                const float4* __restrict__ wv, const float4* __restrict__ woin,
                                uint2* __restrict__ w3, uint2* __restrict__ wo)
{
    const int nq = HID * HID / 4;
    const int nk = KVDIM * HID / 4;
    const int n3 = nq + 2 * nk;
    const int tot = n3 + nq;
    int i = blockIdx.x * blockDim.x + threadIdx.x;
    if (i >= tot) return;
    float4 v;
    uint2* dst;
    int oi;
    if (i < nq)            { v = wq[i];            dst = w3; oi = i; }
    else if (i < nq + nk)  { v = wk[i - nq];       dst = w3; oi = i; }
    else if (i < n3)       { v = wv[i - nq - nk];  dst = w3; oi = i; }
    else                   { v = woin[i - n3];     dst = wo; oi = i - n3; }
    __half2 h0 = __floats2half2_rn(v.x, v.y);
    __half2 h1 = __floats2half2_rn(v.z, v.w);
    uint2 H = {*reinterpret_cast<uint32_t*>(&h0), *reinterpret_cast<uint32_t*>(&h1)};
    dst[oi] = H;
}

// ============================================================================
// RoPE table
// ============================================================================
__global__ void rope_table(float* __restrict__ ct, float* __restrict__ st)
{
    int t = blockIdx.x * blockDim.x + threadIdx.x;
    if (t >= S_LEN * 32) return;
    int pos  = t >> 5;
    int pair = t & 31;
    float inv = (float)exp(-(double)pair * (9.210340371976184 / 32.0));
    float a = (float)pos * inv;
    float s, c;
    sincosf(a, &s, &c);
    ct[t] = c;
    st[t] = s;
}

// ============================================================================
// fp16 1-term GEMM via mma.sync, 2-stage cp.async (2 CTAs/SM),
// 4x2 warp grid (warp tile 32x64), 256 threads.
// qkv_mode: fused rope + single-fp16 epilogue for Q, K, V.
// ============================================================================
#define BM 128
#define BN 128
#define BK 32
#define ROWB   80
#define ASZ    (128 * ROWB)
#define STAGE  (2 * ASZ)                 // A, B tile slots
#define GEMM_SMEM (2 * STAGE)            // 40960 B

__global__ __launch_bounds__(256) void gemm_mma(
    const __half* __restrict__ A, const __half* __restrict__ B,
    float* __restrict__ C, int M, int N, int K,
    int qkv_mode,
    const float* __restrict__ rc, const float* __restrict__ rs,
    __half* __restrict__ q16, __half* __restrict__ k16, __half* __restrict__ v16)
{
    extern __shared__ char smem[];
    const uint32_t sbase = smem_to_u32(smem);

    const int tid  = threadIdx.x;
    const int wid  = tid >> 5;
    const int lane = tid & 31;
    const int wm   = wid >> 1;        // 0..3 (row band)
    const int wn   = wid & 1;         // 0..1 (col band, 64 cols = one head)
    const int bm   = blockIdx.y * BM;
    const int bn   = blockIdx.x * BN;

    const __half* gA = A + (size_t)bm * K;
    const __half* gB = B + (size_t)bn * K;

    const int NC = K / BK;

    const int lr  = tid >> 2;
    const int lsg = tid & 3;
    auto issue = [&](int kc, int buf) {
        const uint32_t sb = sbase + buf * STAGE;
        const size_t kofs = (size_t)kc * BK + lsg * 8;
#pragma unroll
        for (int t = 0; t < 2; ++t) {
            int r = lr + t * 64;
            uint32_t so = (uint32_t)(r * ROWB + lsg * 16);
            size_t g = (size_t)r * K + kofs;
            CP_ASYNC16(sb + so,       gA + g);
            CP_ASYNC16(sb + ASZ + so, gB + g);
        }
        CP_COMMIT();
    };

    float acc[2][8][4];
#pragma unroll
    for (int i = 0; i < 2; ++i)
#pragma unroll
        for (int j = 0; j < 8; ++j)
#pragma unroll
            for (int c = 0; c < 4; ++c) acc[i][j][c] = 0.f;

    const uint32_t a_row  = (uint32_t)(wm * 32 + (lane & 15));
    const uint32_t a_colb = (uint32_t)((lane >> 4) * 16);
    const uint32_t bp_row = (uint32_t)(wn * 64 + ((lane >> 4) << 3) + (lane & 7));
    const uint32_t bp_sel = (uint32_t)(((lane >> 3) & 1) * 16);

    issue(0, 0);
    issue(1, 1);

    for (int kt = 0; kt < NC; ++kt) {
        const int buf = kt & 1;
        if (kt + 2 <= NC) { CP_WAIT(1); }
        else              { CP_WAIT(0); }
        __syncthreads();

        const uint32_t sA = sbase + buf * STAGE;
        const uint32_t sB = sA + ASZ;

#pragma unroll
        for (int ks = 0; ks < 2; ++ks) {
            const uint32_t kofs = ks * 32;

            uint32_t ar[2][4], bb[4][4];
#pragma unroll
            for (int mt = 0; mt < 2; ++mt) {
                uint32_t off = (a_row + mt * 16) * ROWB + a_colb + kofs;
                ldsm_x4(ar[mt], sA + off);
            }
#pragma unroll
            for (int ntp = 0; ntp < 4; ++ntp) {
                uint32_t off = (bp_row + ntp * 16) * ROWB + bp_sel + kofs;
                ldsm_x4(bb[ntp], sB + off);
            }
#pragma unroll
            for (int mt = 0; mt < 2; ++mt)
#pragma unroll
                for (int nt = 0; nt < 8; ++nt) {
                    const uint32_t* bf = &bb[nt >> 1][(nt & 1) * 2];
                    mma16816(acc[mt][nt], ar[mt], bf);
                }
        }
        __syncthreads();

        if (kt + 2 < NC) issue(kt + 2, buf);
    }

    const int er = lane >> 2;
    const int ec = (lane & 3) * 2;

    if (!qkv_mode) {
#pragma unroll
        for (int mt = 0; mt < 2; ++mt) {
            const int row0 = bm + wm * 32 + mt * 16 + er;
#pragma unroll
            for (int nt = 0; nt < 8; ++nt) {
                const int col = bn + wn * 64 + nt * 8 + ec;
                float2 v0 = {acc[mt][nt][0], acc[mt][nt][1]};
                float2 v1 = {acc[mt][nt][2], acc[mt][nt][3]};
                *(float2*)(C + (size_t)row0 * N + col)       = v0;
                *(float2*)(C + (size_t)(row0 + 8) * N + col) = v1;
            }
        }
        return;
    }

    // ---- fused QKV epilogue: rope + single-fp16 conversion ----
    const int gc0 = bn + wn * 64;

    if (gc0 < HID + KVDIM) {
        // Q or K head: rope + single fp16
        __half* dst;
        size_t stride;
        int cb;
        if (gc0 < HID) { dst = q16; stride = HID;   cb = gc0; }
        else           { dst = k16; stride = KVDIM; cb = gc0 - HID; }
#pragma unroll
        for (int mt = 0; mt < 2; ++mt) {
            const int r0 = bm + wm * 32 + mt * 16 + er;
            const int r1 = r0 + 8;
            const int p0 = r0 & (S_LEN - 1), p1 = r1 & (S_LEN - 1);
#pragma unroll
            for (int nt = 0; nt < 4; ++nt) {
                const int d = nt * 8 + ec;
                float cv00 = rc[p0 * 32 + d],     sv00 = rs[p0 * 32 + d];
                float cv01 = rc[p0 * 32 + d + 1], sv01 = rs[p0 * 32 + d + 1];
                float cv10 = rc[p1 * 32 + d],     sv10 = rs[p1 * 32 + d];
                float cv11 = rc[p1 * 32 + d + 1], sv11 = rs[p1 * 32 + d + 1];
                float x00 = acc[mt][nt][0],     x01 = acc[mt][nt][1];
                float x10 = acc[mt][nt][2],     x11 = acc[mt][nt][3];
                float z00 = acc[mt][nt + 4][0], z01 = acc[mt][nt + 4][1];
                float z10 = acc[mt][nt + 4][2], z11 = acc[mt][nt + 4][3];
                __half2 v;
                v = __floats2half2_rn(x00 * cv00 - z00 * sv00, x01 * cv01 - z01 * sv01);
                *(__half2*)(dst + (size_t)r0 * stride + cb + d) = v;
                v = __floats2half2_rn(z00 * cv00 + x00 * sv00, z01 * cv01 + x01 * sv01);
                *(__half2*)(dst + (size_t)r0 * stride + cb + d + 32) = v;
                v = __floats2half2_rn(x10 * cv10 - z10 * sv10, x11 * cv11 - z11 * sv11);
                *(__half2*)(dst + (size_t)r1 * stride + cb + d) = v;
                v = __floats2half2_rn(z10 * cv10 + x10 * sv10, z11 * cv11 + x11 * sv11);
                *(__half2*)(dst + (size_t)r1 * stride + cb + d + 32) = v;
            }
        }
    } else {
        const int cb = gc0 - HID - KVDIM;
#pragma unroll
        for (int mt = 0; mt < 2; ++mt) {
            const int r0 = bm + wm * 32 + mt * 16 + er;
            const int r1 = r0 + 8;
#pragma unroll
            for (int nt = 0; nt < 8; ++nt) {
                const int d = nt * 8 + ec;
                __half2 v;
                v = __floats2half2_rn(acc[mt][nt][0], acc[mt][nt][1]);
                *(__half2*)(v16 + (size_t)r0 * KVDIM + cb + d) = v;
                v = __floats2half2_rn(acc[mt][nt][2], acc[mt][nt][3]);
                *(__half2*)(v16 + (size_t)r1 * KVDIM + cb + d) = v;
            }
        }
    }
}

// ============================================================================
// Tensor-core flash attention (causal): all single-fp16 operands, fp32 accum.
// ============================================================================
#define AT_ROWB 144
#define AT_TILE (64 * AT_ROWB)
#define AT_QTILE (128 * AT_ROWB)
#define ATTN_SMEM (AT_QTILE + 4 * AT_TILE)   // 55296 B

__global__ __launch_bounds__(256) void attn_mma(
    const __half* __restrict__ q16,
    const __half* __restrict__ k16, const __half* __restrict__ v16,
    __half* __restrict__ oa)
{
    extern __shared__ char smem[];
    const uint32_t sbase = smem_to_u32(smem);

    const int qt  = (int)(gridDim.x - 1 - blockIdx.x);   // heavy-first
    const int h   = blockIdx.y;
    const int b   = blockIdx.z;
    const int kvh = h >> 2;
    const int q0  = qt << 7;
    const int tid = threadIdx.x;
    const int warp = tid >> 5;
    const int lane = tid & 31;

    const uint32_t sQ = sbase;
    auto kvtile = [&](int buf, int t) -> uint32_t {
        return sbase + AT_QTILE + (buf * 2 + t) * AT_TILE;
    };

    {   // Q loader: 256 threads, row = tid/2, 4 segs
        const int lrow = tid >> 1;
        const int lsg  = (tid & 1) * 4;
        const size_t grow = (size_t)(b * S_LEN + q0 + lrow) * HID + h * HDIM;
#pragma unroll
        for (int i = 0; i < 4; ++i) {
            int seg = lsg + i;
            uint32_t so = (uint32_t)(lrow * AT_ROWB + seg * 16);
            CP_ASYNC16(sQ + so, q16 + grow + seg * 8);
        }
        CP_COMMIT();
    }

    const int krow = tid >> 2;
    const int ksg  = (tid & 3) * 2;
    auto issue_kv = [&](int kt, int buf) {
        const size_t grow = (size_t)(b * S_LEN + kt * 64 + krow) * KVDIM + kvh * HDIM;
        const uint32_t t0 = kvtile(buf, 0), t1 = kvtile(buf, 1);
#pragma unroll
        for (int i = 0; i < 2; ++i) {
            int seg = ksg + i;
            uint32_t so = (uint32_t)(krow * AT_ROWB + seg * 16);
            CP_ASYNC16(t0 + so, k16 + grow + seg * 8);
            CP_ASYNC16(t1 + so, v16 + grow + seg * 8);
        }
        CP_COMMIT();
    };

    issue_kv(0, 0);

    const uint32_t a_row  = (uint32_t)(warp * 16 + (lane & 15));
    const uint32_t a_colb = (uint32_t)((lane >> 4) * 16);
    const uint32_t kb_row = (uint32_t)(lane & 7);
    const uint32_t kb_sel = (uint32_t)(((lane >> 3) & 1) * 16);
    const uint32_t v_row  = (uint32_t)(lane & 15);

    const int er = lane >> 2;
    const int ec = (lane & 3) * 2;
    const int qg0 = q0 + warp * 16 + er;
    const int qg1 = qg0 + 8;

    uint32_t qf[4][4];

    float o[8][4];
#pragma unroll
    for (int i = 0; i < 8; ++i)
#pragma unroll
        for (int c = 0; c < 4; ++c) o[i][c] = 0.f;
    float m0 = -INFINITY, m1 = -INFINITY, l0 = 0.f, l1 = 0.f;

    const int NT = 2 * qt + 2;

    for (int kt = 0; kt < NT; ++kt) {
        const int buf = kt & 1;
        if (kt + 1 < NT) { issue_kv(kt + 1, buf ^ 1); CP_WAIT(1); }
        else             { CP_WAIT(0); }
        __syncthreads();

        if (kt == 0) {
#pragma unroll
            for (int ks = 0; ks < 4; ++ks) {
                uint32_t off = a_row * AT_ROWB + a_colb + ks * 32;
                ldsm_x4(qf[ks], sQ + off);
            }
        }

        // ---- S = Q K^T (1-term) ----
        float s[8][4];
#pragma unroll
        for (int nt = 0; nt < 8; ++nt)
#pragma unroll
            for (int c = 0; c < 4; ++c) s[nt][c] = 0.f;

        const uint32_t sK = kvtile(buf, 0);
#pragma unroll
        for (int ks = 0; ks < 4; ++ks) {
            uint32_t kf[8][2];
#pragma unroll
            for (int nt = 0; nt < 8; ++nt)
                ldsm_x2(kf[nt], sK + (nt * 8 + kb_row) * AT_ROWB + kb_sel + ks * 32);
#pragma unroll
            for (int nt = 0; nt < 8; ++nt)
                mma16816(s[nt], qf[ks], kf[nt]);
        }

        const int k0 = kt << 6;
#pragma unroll
        for (int nt = 0; nt < 8; ++nt)
#pragma unroll
            for (int c = 0; c < 4; ++c) s[nt][c] *= 0.125f;

        if (kt >= 2 * qt) {
#pragma unroll
            for (int nt = 0; nt < 8; ++nt) {
                int kg = k0 + nt * 8 + ec;
                if (kg     > qg0) s[nt][0] = -INFINITY;
                if (kg + 1 > qg0) s[nt][1] = -INFINITY;
                if (kg     > qg1) s[nt][2] = -INFINITY;
                if (kg + 1 > qg1) s[nt][3] = -INFINITY;
            }
        }

        // ---- online softmax ----
        float mx0 = -INFINITY, mx1 = -INFINITY;
#pragma unroll
        for (int nt = 0; nt < 8; ++nt) {
            mx0 = fmaxf(mx0, fmaxf(s[nt][0], s[nt][1]));
            mx1 = fmaxf(mx1, fmaxf(s[nt][2], s[nt][3]));
        }
        mx0 = fmaxf(mx0, __shfl_xor_sync(0xffffffffu, mx0, 1));
        mx0 = fmaxf(mx0, __shfl_xor_sync(0xffffffffu, mx0, 2));
        mx1 = fmaxf(mx1, __shfl_xor_sync(0xffffffffu, mx1, 1));
        mx1 = fmaxf(mx1, __shfl_xor_sync(0xffffffffu, mx1, 2));

        float mn0 = fmaxf(m0, mx0), mn1 = fmaxf(m1, mx1);
        float cr0 = __expf(m0 - mn0), cr1 = __expf(m1 - mn1);

        float ls0 = 0.f, ls1 = 0.f;
#pragma unroll
        for (int nt = 0; nt < 8; ++nt) {
            s[nt][0] = __expf(s[nt][0] - mn0);
            s[nt][1] = __expf(s[nt][1] - mn0);
            s[nt][2] = __expf(s[nt][2] - mn1);
            s[nt][3] = __expf(s[nt][3] - mn1);
            ls0 += s[nt][0] + s[nt][1];
            ls1 += s[nt][2] + s[nt][3];
        }
        ls0 += __shfl_xor_sync(0xffffffffu, ls0, 1);
        ls0 += __shfl_xor_sync(0xffffffffu, ls0, 2);
        ls1 += __shfl_xor_sync(0xffffffffu, ls1, 1);
        ls1 += __shfl_xor_sync(0xffffffffu, ls1, 2);
        l0 = l0 * cr0 + ls0;
        l1 = l1 * cr1 + ls1;
        m0 = mn0; m1 = mn1;

#pragma unroll
        for (int nt = 0; nt < 8; ++nt) {
            o[nt][0] *= cr0; o[nt][1] *= cr0;
            o[nt][2] *= cr1; o[nt][3] *= cr1;
        }

        // ---- pack P -> single fp16 fragments ----
        uint32_t ph[4][4];
#pragma unroll
        for (int ks = 0; ks < 4; ++ks) {
            __half2 t;
            t = __floats2half2_rn(s[2 * ks][0],     s[2 * ks][1]);
            ph[ks][0] = *reinterpret_cast<uint32_t*>(&t);
            t = __floats2half2_rn(s[2 * ks][2],     s[2 * ks][3]);
            ph[ks][1] = *reinterpret_cast<uint32_t*>(&t);
            t = __floats2half2_rn(s[2 * ks + 1][0], s[2 * ks + 1][1]);
            ph[ks][2] = *reinterpret_cast<uint32_t*>(&t);
            t = __floats2half2_rn(s[2 * ks + 1][2], s[2 * ks + 1][3]);
            ph[ks][3] = *reinterpret_cast<uint32_t*>(&t);
        }

        // ---- O += P V (1-term) ----
        const uint32_t sV = kvtile(buf, 1);
#pragma unroll
        for (int ks = 0; ks < 4; ++ks) {
            uint32_t vf[8][2];
#pragma unroll
            for (int nt = 0; nt < 8; ++nt)
                ldsm_x2_trans(vf[nt], sV + (ks * 16 + v_row) * AT_ROWB + nt * 16);
#pragma unroll
            for (int nt = 0; nt < 8; ++nt)
                mma16816(o[nt], ph[ks], vf[nt]);
        }
        __syncthreads();
    }

    // ---- epilogue: single fp16 output ----
    const float il0 = 1.f / l0, il1 = 1.f / l1;
    const size_t row0 = (size_t)(b * S_LEN + qg0);
    const size_t row1 = (size_t)(b * S_LEN + qg1);
#pragma unroll
    for (int nt = 0; nt < 8; ++nt) {
        const int col = h * HDIM + nt * 8 + ec;
        __half2 v;
        v = __floats2half2_rn(o[nt][0] * il0, o[nt][1] * il0);
        *(__half2*)(oa + row0 * HID + col) = v;
        v = __floats2half2_rn(o[nt][2] * il1, o[nt][3] * il1);
        *(__half2*)(oa + row1 * HID + col) = v;
    }
}

// ============================================================================
// kernel_launch
// ============================================================================
extern "C" void kernel_launch(void* const* d_in, const int* in_sizes, int n_in,
                              void* d_out, int out_size)
{
    (void)in_sizes; (void)n_in; (void)out_size;
    const float* x  = (const float*)d_in[0];
    const float* Wq = (const float*)d_in[1];
    const float* Wk = (const float*)d_in[2];
    const float* Wv = (const float*)d_in[3];
    const float* Wo = (const float*)d_in[4];
    float* out = (float*)d_out;

    float *rc, *rs;
    cudaGetSymbolAddress((void**)&rc, g_rc);
    cudaGetSymbolAddress((void**)&rs, g_rs);

    __half *x16, *w3, *wo, *a16, *q16, *k16, *v16;
    cudaGetSymbolAddress((void**)&x16, g_x16);
    cudaGetSymbolAddress((void**)&w3,  g_w3);
    cudaGetSymbolAddress((void**)&wo,  g_wo);
    cudaGetSymbolAddress((void**)&a16, g_a16);
    cudaGetSymbolAddress((void**)&q16, g_q16);
    cudaGetSymbolAddress((void**)&k16, g_k16);
    cudaGetSymbolAddress((void**)&v16, g_v16);

    cudaFuncSetAttribute(gemm_mma, cudaFuncAttributeMaxDynamicSharedMemorySize, GEMM_SMEM);
    cudaFuncSetAttribute(attn_mma, cudaFuncAttributeMaxDynamicSharedMemorySize, ATTN_SMEM);

    const int M = MROWS;
    const int nx = M * HID;
    const int nconv = (QKVN * HID + HID * HID) / 4;

    // rope tables
    rope_table<<<(S_LEN * 32 + 255) / 256, 256>>>(rc, rs);

    // x convert (single fp16)
    conv_fp16_v4<<<(nx / 4 + 255) / 256, 256>>>((const float4*)x, (uint2*)x16, nx / 4);

    // all weight converts in one launch
    conv_weights_v4<<<(nconv + 255) / 256, 256>>>(
        (const float4*)Wq, (const float4*)Wk, (const float4*)Wv, (const float4*)Wo,
        (uint2*)w3, (uint2*)wo);

    // fused QKV projection (1-term) with rope + single-fp16 epilogue
    gemm_mma<<<dim3(QKVN / BN, M / BM), 256, GEMM_SMEM>>>(
        x16, w3, nullptr, M, QKVN, HID,
        1, rc, rs, q16, k16, v16);

    // causal flash attention (heavy-first, all 1-term)
    attn_mma<<<dim3(S_LEN / 128, NHEADS, BATCH), 256, ATTN_SMEM>>>(
        q16, k16, v16, a16);

    // output projection (1-term)
    gemm_mma<<<dim3(HID / BN, M / BM), 256, GEMM_SMEM>>>(
        a16, wo, out, M, HID, HID,
        0, nullptr, nullptr, nullptr, nullptr, nullptr);
}